// round 15
// baseline (speedup 1.0000x reference)
#include <cuda_runtime.h>
#include <cuda_bf16.h>
#include <math.h>
#include <stdint.h>

// ---------------- problem constants ----------------
#define Bb 4
#define Ll 512
#define Ee 256
#define Kk 8
#define Dd 6
#define LM 64
#define KN 4
#define Gg 32000
#define KE (Kk*Ee)          // 2048
#define TOK (Bb*Ll)         // 2048

typedef __nv_bfloat16 bf;

// ---------------- scratch (static device memory; no allocations) ----------------
__device__ float g_xsa [TOK*Ee];
__device__ float g_xsad[TOK*Ee];
__device__ float g_t1p [4L*TOK*Ee];                  // kWo split-K partials
__device__ bf    g_xsab[TOK*Ee];                     // xsa bf16 [t][e]
__device__ bf    g_xsat[Ee*TOK];                     // xsa bf16 transposed [e][t]
__device__ bf    g_acat[TOK*768];                    // [t1a | t1b | z] bf16
__device__ bf    g_q2b [TOK*KE];
__device__ bf    g_yb  [TOK*KE];
__device__ bf    g_midb[TOK*KE];
// bf16 weights (prep)
__device__ bf    g_wq [(long)Dd*KE*Ee];
__device__ bf    g_wd [(long)Dd*KE*KE];
__device__ bf    g_wot[(long)Dd*Ee*KE];              // Wo^T  [n=E][k=KE]
__device__ bf    g_wc1[Dd*2*Ee*Ee];                  // [Wt^T][Wtc] as [n][k]
__device__ bf    g_wc2[Dd*Ee*768];                   // [Wtc^T|Wt|Wu] rows n, k=768
// head hi/lo bf16 splits (hi of xsa == xsab/xsat)
__device__ bf    g_ehi[(long)Gg*Ee], g_elo[(long)Gg*Ee];
__device__ bf    g_xhlo[TOK*Ee];
__device__ bf    g_xtlo[Ee*TOK];
__device__ bf    g_wkhi[KN*Ee*Ee],g_wklo[KN*Ee*Ee];
__device__ bf    g_wmhi[Ee*Ee],   g_wmlo[Ee*Ee];     // Wem^T hi/lo
__device__ bf    g_lphi[Bb*LM*Ee],g_lplo[Bb*LM*Ee];
__device__ bf    g_x1hi[Bb*LM*KN*Ee], g_x1lo[Bb*LM*KN*Ee];
__device__ bf    g_shi[(long)Bb*LM*KN*Ll], g_slo[(long)Bb*LM*KN*Ll];
__device__ bf    g_xxhi[Bb*LM*KN*Ee], g_xxlo[Bb*LM*KN*Ee];
__device__ bf    g_vhi[Bb*LM*KN*Ee],  g_vlo[Bb*LM*KN*Ee];
// fused-LSE partials (1024 rows x 250 col-blocks)
__device__ float g_pm[(long)Bb*LM*KN*250];
__device__ float g_ps[(long)Bb*LM*KN*250];
__device__ float g_lse [Bb*LM*KN];
__device__ float g_tval[Bb*LM*KN];

// ---------------- reductions ----------------
__device__ __forceinline__ float warp_sum(float v){
    #pragma unroll
    for (int o=16;o;o>>=1) v += __shfl_xor_sync(0xffffffffu, v, o);
    return v;
}
__device__ float block_sum256(float v){
    __shared__ float sh[8];
    int lane = threadIdx.x & 31, w = threadIdx.x >> 5;
    v = warp_sum(v);
    if (lane==0) sh[w] = v;
    __syncthreads();
    float r = (threadIdx.x < 8) ? sh[threadIdx.x] : 0.f;
    if (w==0){ r = warp_sum(r); if (lane==0) sh[0]=r; }
    __syncthreads();
    float out = sh[0];
    __syncthreads();
    return out;
}

// ---------------- bf16 / mma / cp.async / ldmatrix helpers ----------------
__device__ __forceinline__ uint32_t pk2(float lo, float hi){
    uint32_t r;
    asm("cvt.rn.bf16x2.f32 %0, %1, %2;" : "=r"(r) : "f"(hi), "f"(lo));
    return r;
}
__device__ __forceinline__ void mma_bf16(float* d, const uint32_t* a, const uint32_t* b){
    asm volatile(
      "mma.sync.aligned.m16n8k16.row.col.f32.bf16.bf16.f32 "
      "{%0,%1,%2,%3}, {%4,%5,%6,%7}, {%8,%9}, {%0,%1,%2,%3};\n"
      : "+f"(d[0]),"+f"(d[1]),"+f"(d[2]),"+f"(d[3])
      : "r"(a[0]),"r"(a[1]),"r"(a[2]),"r"(a[3]), "r"(b[0]),"r"(b[1]));
}
__device__ __forceinline__ void cp16b(void* s, const bf* g){
    uint32_t sa = (uint32_t)__cvta_generic_to_shared(s);
    asm volatile("cp.async.ca.shared.global [%0], [%1], 16;\n" :: "r"(sa), "l"(g));
}
__device__ __forceinline__ void cp_commit(){ asm volatile("cp.async.commit_group;\n" ::); }
template<int W> __device__ __forceinline__ void cp_wait(){ asm volatile("cp.async.wait_group %0;\n" :: "n"(W)); }
__device__ __forceinline__ uint32_t s2u(const void* p){
    uint32_t a;
    asm("{ .reg .u64 t; cvta.to.shared.u64 t, %1; cvt.u32.u64 %0, t; }" : "=r"(a) : "l"(p));
    return a;
}
__device__ __forceinline__ void ldsm4(uint32_t& r0, uint32_t& r1, uint32_t& r2, uint32_t& r3,
                                      uint32_t addr){
    asm volatile("ldmatrix.sync.aligned.m8n8.x4.shared.b16 {%0,%1,%2,%3}, [%4];"
        : "=r"(r0),"=r"(r1),"=r"(r2),"=r"(r3) : "r"(addr));
}
__device__ __forceinline__ void ols_merge(float& m, float& s, float mo, float so){
    float mn = fmaxf(m, mo);
    s = s*expf(m - mn) + so*expf(mo - mn);
    m = mn;
}

// PMODE output index mapping (element index):
template<int PMODE>
__device__ __forceinline__ long out_index(int r, int c, int bz, int N, long sC){
    if (PMODE==0) return (long)bz*sC + (long)r*N + c;
    if (PMODE==1) return (((long)(r>>9))<<20) + ((long)(r&511)<<11) + c;
    if (PMODE==2) return (((long)(bz*512 + (r>>3)))<<11) + ((long)(r&7)<<8) + c;
    if (PMODE==3) return (((long)(r>>6))<<16) + ((long)(r&63)<<10) + c;
    return (long)r*768 + ((long)bz<<8) + c;
}

// ---------------- unified bf16 tensor-core GEMM (ldmatrix, templated K-chunk) ----------------
// KCH: 32 -> pitch 20 / 3-stage; 64 -> pitch 36 / 2-stage; 128 -> pitch 68 / 2-stage.
// All pitches are = 4 (mod 32) words -> ldmatrix conflict-free (8 rows hit 8 distinct
// 4-bank groups).
template<int BM,int BN,int WM,int WN,int KCH,bool RELU,bool BIAS,int PMODE,int ROLLMODE,bool COMP,int OUTMODE>
__global__ __launch_bounds__(256, 2)
void bgemm_k(const bf* __restrict__ A, const bf* __restrict__ Alo,
             const bf* __restrict__ B, const bf* __restrict__ Blo,
             const float* __restrict__ bias,
             float* __restrict__ C, bf* __restrict__ Cb, bf* __restrict__ Clo,
             int M, int N, int Kd, int lda, int ldb,
             long sA, long sB, long sC, int rollShift)
{
    constexpr int P    = KCH/2 + 4;          // words per smem row
    constexpr int CH   = KCH/8;              // 16B chunks per row
    constexpr int NSTG = (KCH>=64) ? 2 : 3;
    constexpr int NST  = COMP ? 2 : 1;
    constexpr int TA   = BM*P, TB = BN*P;
    constexpr int STG  = NST*(TA+TB);
    constexpr int MI   = WM/16, NI = WN/8;
    constexpr int NJ   = NI/2;
    constexpr int WCOLS = BN/WN;
    constexpr int KS   = KCH/16;

    extern __shared__ uint32_t smw[];
    const uint32_t smem_u = s2u(smw);

    const int bz = blockIdx.z;
    const bf* Ap  = A + (long)bz*sA;
    const bf* Alp = COMP ? Alo + (long)bz*sA : nullptr;
    const bf* Bp  = B + (long)bz*sB;
    const bf* Blp = COMP ? Blo + (long)bz*sB : nullptr;

    int rs = 0;
    if (ROLLMODE==2) rs = (bz==0) ? rollShift : -rollShift;

    const int row0 = blockIdx.y*BM, col0 = blockIdx.x*BN;
    const int tid  = threadIdx.x;
    const int warp = tid >> 5, lane = tid & 31;
    const int wy = warp / WCOLS, wx = warp % WCOLS;
    const int g = lane >> 2, c4 = lane & 3;

    uint32_t aoff[MI];
    #pragma unroll
    for (int mi=0; mi<MI; mi++)
        aoff[mi] = (uint32_t)(((wy*WM + mi*16 + (lane & 15))*P + (lane>>4)*4) * 4);
    uint32_t boff[NJ];
    #pragma unroll
    for (int j=0; j<NJ; j++)
        boff[j] = (uint32_t)(((wx*WN + j*16 + ((lane>>4)<<3) + (lane & 7))*P + ((lane>>3)&1)*4) * 4);

    auto load_tile = [&](int kt, int st){
        uint32_t* base = smw + st*STG;
        uint32_t* Ah = base;
        uint32_t* Al = base + TA;
        uint32_t* Bh = base + NST*TA;
        uint32_t* Bl = Bh + TB;
        const int k0 = kt*KCH;
        #pragma unroll
        for (int i=0;i<BM*CH/256;i++){
            int id = tid + i*256; int r = id/CH, q = id%CH;
            int gr = row0 + r;
            if (ROLLMODE) gr = (gr & ~511) | ((gr - rs) & 511);
            long go = (long)gr*lda + k0 + 8*q;
            cp16b(Ah + r*P + 4*q, Ap + go);
            if (COMP) cp16b(Al + r*P + 4*q, Alp + go);
        }
        #pragma unroll
        for (int i=0;i<BN*CH/256;i++){
            int id = tid + i*256; int n = id/CH, q = id%CH;
            long go = (long)(col0+n)*ldb + k0 + 8*q;
            cp16b(Bh + n*P + 4*q, Bp + go);
            if (COMP) cp16b(Bl + n*P + 4*q, Blp + go);
        }
        cp_commit();
    };

    float acc[MI][NI][4];
    #pragma unroll
    for (int i=0;i<MI;i++)
        #pragma unroll
        for (int j=0;j<NI;j++)
            #pragma unroll
            for (int t=0;t<4;t++) acc[i][j][t]=0.f;

    const int nit = Kd/KCH;
    load_tile(0, 0);
    if (NSTG==3 && nit>1) load_tile(1, 1);

    int st = 0;
    for (int it=0; it<nit; it++){
        if (NSTG==3){
            if (it+2 < nit){ load_tile(it+2, (it+2)%3); cp_wait<2>(); }
            else if (it+1 < nit){ cp_wait<1>(); }
            else { cp_wait<0>(); }
        } else {
            if (it+1 < nit){ load_tile(it+1, (it+1)&1); cp_wait<1>(); }
            else { cp_wait<0>(); }
        }
        __syncthreads();

        const uint32_t AhB = smem_u + (uint32_t)(st*STG*4);
        const uint32_t AlB = AhB + TA*4;
        const uint32_t BhB = AhB + NST*TA*4;
        const uint32_t BlB = BhB + TB*4;

        #pragma unroll
        for (int ks=0; ks<KS; ks++){
            const uint32_t ko = ks*32;
            uint32_t af[MI][4], bfr[NI][2];
            uint32_t afl[COMP?MI:1][4], bfl[COMP?NI:1][2];
            #pragma unroll
            for (int mi=0; mi<MI; mi++){
                ldsm4(af[mi][0], af[mi][1], af[mi][2], af[mi][3], AhB + aoff[mi] + ko);
                if (COMP)
                    ldsm4(afl[mi][0], afl[mi][1], afl[mi][2], afl[mi][3], AlB + aoff[mi] + ko);
            }
            #pragma unroll
            for (int j=0; j<NJ; j++){
                ldsm4(bfr[2*j][0], bfr[2*j][1], bfr[2*j+1][0], bfr[2*j+1][1], BhB + boff[j] + ko);
                if (COMP)
                    ldsm4(bfl[2*j][0], bfl[2*j][1], bfl[2*j+1][0], bfl[2*j+1][1], BlB + boff[j] + ko);
            }
            #pragma unroll
            for (int mi=0; mi<MI; mi++)
                #pragma unroll
                for (int ni=0; ni<NI; ni++){
                    if (COMP){
                        mma_bf16(acc[mi][ni], afl[mi], bfr[ni]);
                        mma_bf16(acc[mi][ni], af[mi], bfl[ni]);
                    }
                    mma_bf16(acc[mi][ni], af[mi], bfr[ni]);
                }
        }
        __syncthreads();
        st = (NSTG==3) ? ((st==2)?0:st+1) : (st^1);
    }

    // ---- epilogue ----
    #pragma unroll
    for (int mi=0; mi<MI; mi++){
        #pragma unroll
        for (int half=0; half<2; half++){
            int r = row0 + wy*WM + mi*16 + g + half*8;
            #pragma unroll
            for (int ni=0; ni<NI; ni++){
                int cc = col0 + wx*WN + ni*8 + 2*c4;
                float v0 = acc[mi][ni][half*2+0];
                float v1 = acc[mi][ni][half*2+1];
                if (BIAS){ v0 += bias[cc]; v1 += bias[cc+1]; }
                if (RELU){ v0 = fmaxf(v0,0.f); v1 = fmaxf(v1,0.f); }
                long idx = out_index<PMODE>(r, cc, bz, N, sC);
                if (OUTMODE==0){
                    *(float2*)(C + idx) = make_float2(v0, v1);
                } else if (OUTMODE==1){
                    *(uint32_t*)(Cb + idx) = pk2(v0, v1);
                } else {
                    bf h0 = __float2bfloat16(v0);
                    bf h1 = __float2bfloat16(v1);
                    union { __nv_bfloat162 b; uint32_t u; } cu;
                    cu.b = __halves2bfloat162(h0, h1);
                    *(uint32_t*)(Cb + idx)  = cu.u;
                    *(uint32_t*)(Clo + idx) = pk2(v0 - __bfloat162float(h0),
                                                  v1 - __bfloat162float(h1));
                }
            }
        }
    }
}

// ---------------- fully fused attention: QK (KCH=64) -> softmax -> P@V ----------------
__global__ __launch_bounds__(512, 1)
void fa_k(const bf* __restrict__ A, const bf* __restrict__ B,
          const bf* __restrict__ Vt, bf* __restrict__ Y,
          long sA, long sB)
{
    constexpr int Pw1 = 36;                  // phase-1 pitch (KCH=64)
    constexpr int TA1 = 64*Pw1, TB1 = 512*Pw1, STG1 = TA1+TB1;
    constexpr int Pw  = 20;                  // phase-2 pitch (P region, V tiles)
    constexpr int PWW = 16*64*Pw;            // P region (20480 words)
    constexpr int TB2 = 256*Pw;              // V tile stage (5120 words)
    extern __shared__ uint32_t smw[];
    const uint32_t smem_u = s2u(smw);

    const int bz = blockIdx.z;
    const bf* Ap = A + (long)bz*sA;
    const bf* Bp = B + (long)bz*sB;
    const int row0 = blockIdx.y*64;
    const int tid = threadIdx.x, warp = tid>>5, lane = tid&31;
    const int g = lane>>2, c4 = lane&3;
    const int wy = warp>>3, wx = warp&7;     // 2 x 8 warps

    uint32_t aoff1[2];
    #pragma unroll
    for (int mi=0;mi<2;mi++)
        aoff1[mi] = (uint32_t)(((wy*32 + mi*16 + (lane & 15))*Pw1 + (lane>>4)*4) * 4);
    uint32_t boff1[4];
    #pragma unroll
    for (int j=0;j<4;j++)
        boff1[j] = (uint32_t)(((wx*64 + j*16 + ((lane>>4)<<3) + (lane & 7))*Pw1 + ((lane>>3)&1)*4) * 4);

    auto load_tile1 = [&](int kt, int st){
        uint32_t* base = smw + st*STG1;
        uint32_t* Ah = base;
        uint32_t* Bh = base + TA1;
        const int k0 = kt*64;
        {   // A: 64 rows x 8 chunks = 512 chunks = 1 pass
            int r = tid>>3, q = tid&7;
            cp16b(Ah + r*Pw1 + 4*q, Ap + (long)(row0+r)*256 + k0 + 8*q);
        }
        #pragma unroll
        for (int i=0;i<8;i++){   // B: 512 rows x 8 chunks = 4096
            int id = tid + i*512; int n = id>>3, q = id&7;
            cp16b(Bh + n*Pw1 + 4*q, Bp + (long)n*256 + k0 + 8*q);
        }
        cp_commit();
    };

    float acc[2][8][4];
    #pragma unroll
    for (int i=0;i<2;i++)
        #pragma unroll
        for (int j=0;j<8;j++)
            #pragma unroll
            for (int t=0;t<4;t++) acc[i][j][t]=0.f;

    {
        const int nit = 4;   // K=256, KCH=64
        load_tile1(0, 0);
        int st = 0;
        for (int it=0; it<nit; it++){
            if (it+1 < nit){ load_tile1(it+1, st^1); cp_wait<1>(); }
            else { cp_wait<0>(); }
            __syncthreads();

            const uint32_t AhB = smem_u + (uint32_t)(st*STG1*4);
            const uint32_t BhB = AhB + TA1*4;
            #pragma unroll
            for (int ks=0; ks<4; ks++){
                const uint32_t ko = ks*32;
                uint32_t af[2][4], bfr[8][2];
                #pragma unroll
                for (int mi=0; mi<2; mi++)
                    ldsm4(af[mi][0], af[mi][1], af[mi][2], af[mi][3], AhB + aoff1[mi] + ko);
                #pragma unroll
                for (int j=0; j<4; j++)
                    ldsm4(bfr[2*j][0], bfr[2*j][1], bfr[2*j+1][0], bfr[2*j+1][1], BhB + boff1[j] + ko);
                #pragma unroll
                for (int mi=0; mi<2; mi++)
                    #pragma unroll
                    for (int ni=0; ni<8; ni++)
                        mma_bf16(acc[mi][ni], af[mi], bfr[ni]);
            }
            __syncthreads();
            st ^= 1;
        }
    }

    // softmax (scale 1/16)
    float* red_m = (float*)(smw + PWW + 2*TB2);
    float* red_s = red_m + 64*8;
    #pragma unroll
    for (int mi=0; mi<2; mi++){
        #pragma unroll
        for (int half=0; half<2; half++){
            float mx = -INFINITY;
            #pragma unroll
            for (int ni=0; ni<8; ni++)
                mx = fmaxf(mx, fmaxf(acc[mi][ni][half*2], acc[mi][ni][half*2+1]));
            mx *= 0.0625f;
            float s = 0.f;
            #pragma unroll
            for (int ni=0; ni<8; ni++){
                s += expf(acc[mi][ni][half*2+0]*0.0625f - mx);
                s += expf(acc[mi][ni][half*2+1]*0.0625f - mx);
            }
            float m = mx;
            #pragma unroll
            for (int o=1; o<=2; o<<=1){
                float mo = __shfl_xor_sync(0xffffffffu, m, o);
                float so = __shfl_xor_sync(0xffffffffu, s, o);
                ols_merge(m, s, mo, so);
            }
            int rt = wy*32 + mi*16 + half*8 + g;
            if (c4==0){ red_m[rt*8+wx] = m; red_s[rt*8+wx] = s; }
        }
    }
    __syncthreads();
    if (tid < 64){
        float M = red_m[tid*8], S = red_s[tid*8];
        #pragma unroll
        for (int i=1;i<8;i++) ols_merge(M, S, red_m[tid*8+i], red_s[tid*8+i]);
        red_m[tid*8] = M;
        red_s[tid*8] = 1.f/S;
    }
    __syncthreads();
    #pragma unroll
    for (int mi=0; mi<2; mi++){
        #pragma unroll
        for (int half=0; half<2; half++){
            int rt = wy*32 + mi*16 + half*8 + g;
            float M = red_m[rt*8], inv = red_s[rt*8];
            #pragma unroll
            for (int ni=0; ni<8; ni++){
                int c = wx*64 + ni*8 + 2*c4;
                float p0 = expf(acc[mi][ni][half*2+0]*0.0625f - M)*inv;
                float p1 = expf(acc[mi][ni][half*2+1]*0.0625f - M)*inv;
                smw[(c>>5)*(64*Pw) + rt*Pw + ((c&31)>>1)] = pk2(p0, p1);
            }
        }
    }
    __syncthreads();

    // phase 2: y(64x256) = P @ V^T, K=512
    const int wx2 = warp&7, wy2 = warp>>3;
    uint32_t aoff2[2];
    #pragma unroll
    for (int mi=0;mi<2;mi++)
        aoff2[mi] = (uint32_t)(((wy2*32 + mi*16 + (lane & 15))*Pw + (lane>>4)*4) * 4);
    uint32_t boff2a[2];
    #pragma unroll
    for (int j=0;j<2;j++)
        boff2a[j] = (uint32_t)(((wx2*32 + j*16 + ((lane>>4)<<3) + (lane & 7))*Pw + ((lane>>3)&1)*4) * 4);

    auto load_v = [&](int kt, int st){
        uint32_t* Bh = smw + PWW + st*TB2;
        const int k0 = kt*32;
        #pragma unroll
        for (int i=0;i<2;i++){
            int id = tid + i*512; int n = id>>2, q = id&3;
            cp16b(Bh + n*Pw + 4*q, Vt + (long)n*TOK + bz*512 + k0 + 8*q);
        }
        cp_commit();
    };

    float acc2[2][4][4];
    #pragma unroll
    for (int i=0;i<2;i++)
        #pragma unroll
        for (int j=0;j<4;j++)
            #pragma unroll
            for (int t=0;t<4;t++) acc2[i][j][t]=0.f;

    {
        const int nit = 16;  // K=512
        load_v(0, 0);
        int st = 0;
        for (int it=0; it<nit; it++){
            if (it+1 < nit){ load_v(it+1, st^1); cp_wait<1>(); }
            else { cp_wait<0>(); }
            __syncthreads();

            const uint32_t AB = smem_u + (uint32_t)(it*64*Pw*4);
            const uint32_t BB = smem_u + (uint32_t)((PWW + st*TB2)*4);
            #pragma unroll
            for (int ks=0; ks<2; ks++){
                const uint32_t ko = ks*32;
                uint32_t af[2][4], bfr[4][2];
                #pragma unroll
                for (int mi=0; mi<2; mi++)
                    ldsm4(af[mi][0], af[mi][1], af[mi][2], af[mi][3], AB + aoff2[mi] + ko);
                #pragma unroll
                for (int j=0; j<2; j++)
                    ldsm4(bfr[2*j][0], bfr[2*j][1], bfr[2*j+1][0], bfr[2*j+1][1], BB + boff2a[j] + ko);
                #pragma unroll
                for (int mi=0; mi<2; mi++)
                    #pragma unroll
                    for (int ni=0; ni<4; ni++)
                        mma_bf16(acc2[mi][ni], af[mi], bfr[ni]);
            }
            __syncthreads();
            st ^= 1;
        }
    }

    #pragma unroll
    for (int mi=0; mi<2; mi++){
        #pragma unroll
        for (int half=0; half<2; half++){
            int r = row0 + wy2*32 + mi*16 + g + half*8;
            #pragma unroll
            for (int ni=0; ni<4; ni++){
                int cc = wx2*32 + ni*8 + 2*c4;
                long idx = (((long)(bz*512 + (r>>3)))<<11) + ((long)(r&7)<<8) + cc;
                *(uint32_t*)(Y + idx) = pk2(acc2[mi][ni][half*2+0], acc2[mi][ni][half*2+1]);
            }
        }
    }
}

// ---------------- fused logits GEMM + online-LSE partials (COMP, 128x128, KCH=64) ----------------
__global__ __launch_bounds__(256, 1)
void glse_k(const bf* __restrict__ A, const bf* __restrict__ Alo,
            const bf* __restrict__ B, const bf* __restrict__ Blo,
            float* __restrict__ pm, float* __restrict__ ps)
{
    constexpr int Pw = 36;
    constexpr int TA = 128*Pw, TB = 128*Pw;
    constexpr int STG = 2*(TA+TB);
    extern __shared__ uint32_t smw[];
    const uint32_t smem_u = s2u(smw);

    const int row0 = blockIdx.y*128, col0 = blockIdx.x*128, bx = blockIdx.x;
    const int tid = threadIdx.x, warp = tid>>5, lane = tid&31;
    const int wy = warp>>2, wx = warp&3;     // WM=64, WN=32
    const int g = lane>>2, c4 = lane&3;

    uint32_t aoff[4];
    #pragma unroll
    for (int mi=0;mi<4;mi++)
        aoff[mi] = (uint32_t)(((wy*64 + mi*16 + (lane & 15))*Pw + (lane>>4)*4) * 4);
    uint32_t boff[2];
    #pragma unroll
    for (int j=0;j<2;j++)
        boff[j] = (uint32_t)(((wx*32 + j*16 + ((lane>>4)<<3) + (lane & 7))*Pw + ((lane>>3)&1)*4) * 4);

    auto load_tile = [&](int kt, int st){
        uint32_t* base = smw + st*STG;
        uint32_t* Ah = base;
        uint32_t* Al = base + TA;
        uint32_t* Bh = base + 2*TA;
        uint32_t* Bl = Bh + TB;
        const int k0 = kt*64;
        #pragma unroll
        for (int i=0;i<4;i++){
            int id = tid + i*256; int r = id>>3, q = id&7;
            long go = (long)(row0+r)*256 + k0 + 8*q;
            cp16b(Ah + r*Pw + 4*q, A + go);
            cp16b(Al + r*Pw + 4*q, Alo + go);
            long gb = (long)(col0+r)*256 + k0 + 8*q;
            cp16b(Bh + r*Pw + 4*q, B + gb);
            cp16b(Bl + r*Pw + 4*q, Blo + gb);
        }
        cp_commit();
    };

    float acc[4][4][4];
    #pragma unroll
    for (int i=0;i<4;i++)
        #pragma unroll
        for (int j=0;j<4;j++)
            #pragma unroll
            for (int t=0;t<4;t++) acc[i][j][t]=0.f;

    const int nit = 4;   // K=256, KCH=64
    load_tile(0, 0);
    int st = 0;
    for (int it=0; it<nit; it++){
        if (it+1 < nit){ load_tile(it+1, (it+1)&1); cp_wait<1>(); }
        else { cp_wait<0>(); }
        __syncthreads();

        const uint32_t AhB = smem_u + (uint32_t)(st*STG*4);
        const uint32_t AlB = AhB + TA*4;
        const uint32_t BhB = AhB + 2*TA*4;
        const uint32_t BlB = BhB + TB*4;
        #pragma unroll
        for (int ks=0; ks<4; ks++){
            const uint32_t ko = ks*32;
            uint32_t af[4][4], afl[4][4], bfr[4][2], bfl[4][2];
            #pragma unroll
            for (int mi=0; mi<4; mi++){
                ldsm4(af[mi][0], af[mi][1], af[mi][2], af[mi][3], AhB + aoff[mi] + ko);
                ldsm4(afl[mi][0], afl[mi][1], afl[mi][2], afl[mi][3], AlB + aoff[mi] + ko);
            }
            #pragma unroll
            for (int j=0; j<2; j++){
                ldsm4(bfr[2*j][0], bfr[2*j][1], bfr[2*j+1][0], bfr[2*j+1][1], BhB + boff[j] + ko);
                ldsm4(bfl[2*j][0], bfl[2*j][1], bfl[2*j+1][0], bfl[2*j+1][1], BlB + boff[j] + ko);
            }
            #pragma unroll
            for (int mi=0; mi<4; mi++)
                #pragma unroll
                for (int ni=0; ni<4; ni++){
                    mma_bf16(acc[mi][ni], afl[mi], bfr[ni]);
                    mma_bf16(acc[mi][ni], af[mi], bfl[ni]);
                    mma_bf16(acc[mi][ni], af[mi], bfr[ni]);
                }
        }
        __syncthreads();
        st ^= 1;
    }

    float* red_m = (float*)smw;       // [128][4]
    float* red_s = red_m + 128*4;
    #pragma unroll
    for (int mi=0; mi<4; mi++){
        #pragma unroll
        for (int half=0; half<2; half++){
            float mx = -INFINITY;
            #pragma unroll
            for (int ni=0; ni<4; ni++)
                mx = fmaxf(mx, fmaxf(acc[mi][ni][half*2], acc[mi][ni][half*2+1]));
            float s = 0.f;
            #pragma unroll
            for (int ni=0; ni<4; ni++){
                s += expf(acc[mi][ni][half*2+0]-mx);
                s += expf(acc[mi][ni][half*2+1]-mx);
            }
            float m = mx;
            #pragma unroll
            for (int o=1; o<=2; o<<=1){
                float mo = __shfl_xor_sync(0xffffffffu, m, o);
                float so = __shfl_xor_sync(0xffffffffu, s, o);
                ols_merge(m, s, mo, so);
            }
            int rt = wy*64 + mi*16 + half*8 + g;
            if (c4==0){ red_m[rt*4+wx] = m; red_s[rt*4+wx] = s; }
        }
    }
    __syncthreads();
    if (tid < 128){
        float M = red_m[tid*4], S = red_s[tid*4];
        #pragma unroll
        for (int i=1;i<4;i++) ols_merge(M, S, red_m[tid*4+i], red_s[tid*4+i]);
        long idx = (long)(row0+tid)*250 + bx;
        pm[idx] = M;
        ps[idx] = S;
    }
}

// merge 250 partials per row -> lse
__global__ void lse_red_k(const float* __restrict__ pm, const float* __restrict__ ps,
                          float* __restrict__ lse){
    int row = blockIdx.x*8 + (threadIdx.x>>5);
    int lane = threadIdx.x & 31;
    float m = -INFINITY, s = 0.f;
    for (int i=lane; i<250; i+=32)
        ols_merge(m, s, pm[(long)row*250+i], ps[(long)row*250+i]);
    #pragma unroll
    for (int o=16;o;o>>=1){
        float mo = __shfl_xor_sync(0xffffffffu, m, o);
        float so = __shfl_xor_sync(0xffffffffu, s, o);
        ols_merge(m, s, mo, so);
    }
    if (lane==0) lse[row] = m + logf(s);
}

// exact fp32 target logit
__global__ void tval_k(const bf* __restrict__ vhi, const bf* __restrict__ vlo,
                       const bf* __restrict__ ehi, const bf* __restrict__ elo,
                       const int* __restrict__ unmasked, const int* __restrict__ mask,
                       float* __restrict__ tval){
    int row = blockIdx.x;
    int b = row >> 8, n = row & 255, j = n >> 2;
    int tg = unmasked[b*Ll + mask[b*LM + j]];
    long vi = (long)row*Ee + threadIdx.x;
    long ei = (long)tg*Ee + threadIdx.x;
    float v = (__bfloat162float(vhi[vi]) + __bfloat162float(vlo[vi]))
            * (__bfloat162float(ehi[ei]) + __bfloat162float(elo[ei]));
    float s = block_sum256(v);
    if (threadIdx.x==0) tval[row] = s;
}

// ---------------- prep kernels ----------------
__global__ void prep_w_k(const float* __restrict__ Wt, const float* __restrict__ Wtc,
                         const float* __restrict__ Wu,
                         bf* __restrict__ wc1, bf* __restrict__ wc2)
{
    long idx = (long)blockIdx.x*1024 + threadIdx.x;
    if (idx >= (long)Dd*5*65536) return;
    int d = idx / (5*65536);
    int r = idx % (5*65536);
    int which = r / 65536;
    int e = r % 65536;
    int n = e >> 8, k = e & 255;
    long wb = (long)d*65536;
    if      (which==0) wc1[(long)d*131072 +         n*256+k] = __float2bfloat16(Wt [wb + (long)k*256 + n]);
    else if (which==1) wc1[(long)d*131072 + 65536 + n*256+k] = __float2bfloat16(Wtc[wb + (long)n*256 + k]);
    else if (which==2) wc2[(long)d*196608 + (long)n*768 +       k] = __float2bfloat16(Wtc[wb + (long)k*256 + n]);
    else if (which==3) wc2[(long)d*196608 + (long)n*768 + 256 + k] = __float2bfloat16(Wt [wb + (long)n*256 + k]);
    else               wc2[(long)d*196608 + (long)n*768 + 512 + k] = __float2bfloat16(Wu [wb + (long)n*256 + k]);
}

__global__ void conv_b4(const float4* __restrict__ in, uint2* __restrict__ outp, long n4){
    long i = (long)blockIdx.x*256 + threadIdx.x;
    if (i >= n4) return;
    float4 v = in[i];
    uint2 o; o.x = pk2(v.x, v.y); o.y = pk2(v.z, v.w);
    outp[i] = o;
}

__global__ void split_b4(const float4* __restrict__ in, uint2* __restrict__ hi,
                         uint2* __restrict__ lo, long n4){
    long i = (long)blockIdx.x*256 + threadIdx.x;
    if (i >= n4) return;
    float4 v = in[i];
    bf hx=__float2bfloat16(v.x), hy=__float2bfloat16(v.y);
    bf hz=__float2bfloat16(v.z), hw=__float2bfloat16(v.w);
    union { __nv_bfloat162 b; uint32_t u; } c0, c1;
    c0.b = __halves2bfloat162(hx, hy);
    c1.b = __halves2bfloat162(hz, hw);
    uint2 h; h.x=c0.u; h.y=c1.u;
    uint2 l;
    l.x = pk2(v.x-__bfloat162float(hx), v.y-__bfloat162float(hy));
    l.y = pk2(v.z-__bfloat162float(hz), v.w-__bfloat162float(hw));
    hi[i]=h; lo[i]=l;
}

__global__ void split_lo4(const float4* __restrict__ in, uint2* __restrict__ lo, long n4){
    long i = (long)blockIdx.x*256 + threadIdx.x;
    if (i >= n4) return;
    float4 v = in[i];
    bf hx=__float2bfloat16(v.x), hy=__float2bfloat16(v.y);
    bf hz=__float2bfloat16(v.z), hw=__float2bfloat16(v.w);
    uint2 l;
    l.x = pk2(v.x-__bfloat162float(hx), v.y-__bfloat162float(hy));
    l.y = pk2(v.z-__bfloat162float(hz), v.w-__bfloat162float(hw));
    lo[i]=l;
}

__global__ void t32_f2b(const float* __restrict__ src, bf* __restrict__ dst, int R, int C){
    __shared__ bf t[32][33];
    const float* s = src + (long)blockIdx.z*R*C;
    bf* d = dst + (long)blockIdx.z*R*C;
    int r0 = blockIdx.x*32, c0 = blockIdx.y*32;
    int tx = threadIdx.x & 31, ty = threadIdx.x >> 5;
    #pragma unroll
    for (int i=0;i<4;i++) t[ty+8*i][tx] = __float2bfloat16(s[(long)(r0+ty+8*i)*C + c0+tx]);
    __syncthreads();
    #pragma unroll
    for (int i=0;i<4;i++) d[(long)(c0+ty+8*i)*R + r0+tx] = t[tx][ty+8*i];
}

__global__ void t32_f2b2(const float* __restrict__ src, bf* __restrict__ dh,
                         bf* __restrict__ dl, int R, int C){
    __shared__ bf th[32][33];
    __shared__ bf tl[32][33];
    int r0 = blockIdx.x*32, c0 = blockIdx.y*32;
    int tx = threadIdx.x & 31, ty = threadIdx.x >> 5;
    #pragma unroll
    for (int i=0;i<4;i++){
        float v = src[(long)(r0+ty+8*i)*C + c0+tx];
        bf h = __float2bfloat16(v);
        th[ty+8*i][tx] = h;
        tl[ty+8*i][tx] = __float2bfloat16(v - __bfloat162float(h));
    }
    __syncthreads();
    #pragma unroll
    for (int i=0;i<4;i++){
        dh[(long)(c0+ty+8*i)*R + r0+tx] = th[tx][ty+8*i];
        dl[(long)(c0+ty+8*i)*R + r0+tx] = tl[tx][ty+8*i];
    }
}

__global__ void transpose_b(const bf* __restrict__ src, bf* __restrict__ dst, int R, int C){
    __shared__ bf t[32][33];
    int r0 = blockIdx.x*32, c0 = blockIdx.y*32;
    int tx = threadIdx.x & 31, ty = threadIdx.x >> 5;
    #pragma unroll
    for (int i=0;i<4;i++) t[ty+8*i][tx] = src[(long)(r0+ty+8*i)*C + c0+tx];
    __syncthreads();
    #pragma unroll
    for (int i=0;i<4;i++) dst[(long)(c0+ty+8*i)*R + r0+tx] = t[tx][ty+8*i];
}

// ---------------- elementwise / reduction kernels ----------------
__global__ void embed_norm_k(const int* __restrict__ masked, const float* __restrict__ embed,
                             float* __restrict__ xsa, bf* __restrict__ xsab,
                             bf* __restrict__ xsat, bf* __restrict__ acat)
{
    int t = blockIdx.x;
    int g = masked[t];
    float v = embed[(long)g*Ee + threadIdx.x];
    float mean = block_sum256(v) * (1.f/Ee);
    float d = v - mean;
    float var = block_sum256(d*d) * (1.f/(Ee-1));
    float o = v / (1.f + sqrtf(var));
    xsa [(long)t*Ee + threadIdx.x] = o;
    bf ob = __float2bfloat16(o);
    xsab[(long)t*Ee + threadIdx.x] = ob;
    xsat[(long)threadIdx.x*TOK + t] = ob;
    acat[(long)t*768 + 512 + threadIdx.x] = ob;
}

__global__ void update_norm_k(const float* __restrict__ xsad, const float* __restrict__ t1p,
                              float* __restrict__ xsa, bf* __restrict__ xsab,
                              bf* __restrict__ xsat)
{
    long idx = (long)blockIdx.x*Ee + threadIdx.x;
    const long S = (long)TOK*Ee;
    float u = xsad[idx] + t1p[idx] + t1p[idx+S] + t1p[idx+2*S] + t1p[idx+3*S];
    float mean = block_sum256(u) * (1.f/Ee);
    float d = u - mean;
    float var = block_sum256(d*d) * (1.f/(Ee-1));
    float un = u / (1.f + sqrtf(var));
    float w = xsa[idx] + 0.05f * un;
    float mean2 = block_sum256(w) * (1.f/Ee);
    float d2 = w - mean2;
    float var2 = block_sum256(d2*d2) * (1.f/(Ee-1));
    float o = w / (1.f + sqrtf(var2));
    xsa[idx]  = o;
    bf ob = __float2bfloat16(o);
    xsab[idx] = ob;
    xsat[(long)threadIdx.x*TOK + blockIdx.x] = ob;
}

__global__ void gather_split_k(const int* __restrict__ mask, const float* __restrict__ xsa,
                               bf* __restrict__ hi, bf* __restrict__ lo){
    int r = blockIdx.x; int b = r >> 6; int p = mask[r];
    float v = xsa[(long)(b*Ll + p)*Ee + threadIdx.x];
    bf h = __float2bfloat16(v);
    hi[(long)r*Ee + threadIdx.x] = h;
    lo[(long)r*Ee + threadIdx.x] = __float2bfloat16(v - __bfloat162float(h));
}

__global__ void final_k(const float* __restrict__ tval, const float* __restrict__ lse,
                        float* __restrict__ out)
{
    int b = blockIdx.x, j = threadIdx.x;   // 64 threads
    float a[KN]; float m = -INFINITY;
    #pragma unroll
    for (int kn=0;kn<KN;kn++){
        int r = ((b << 6) + j) * KN + kn;
        a[kn] = tval[r] - lse[r];
        m = fmaxf(m, a[kn]);
    }
    float s = 0.f;
    #pragma unroll
    for (int kn=0;kn<KN;kn++) s += expf(a[kn] - m);
    float cent = m + logf(s) - 1.3862943611198906f;   // - log(4)
    __shared__ float sh[64];
    sh[j] = cent; __syncthreads();
    for (int o=32;o;o>>=1){ if (j<o) sh[j] += sh[j+o]; __syncthreads(); }
    if (j==0) out[b] = -sh[0] / (float)LM;
}

// ---------------- host orchestration ----------------
#define GSYM(p, s) cudaGetSymbolAddress((void**)&p, s)

extern "C" void kernel_launch(void* const* d_in, const int* in_sizes, int n_in,
                              void* d_out, int out_size)
{
    (void)in_sizes; (void)n_in; (void)out_size;
    const int*   masked   = (const int*)  d_in[0];
    const int*   unmasked = (const int*)  d_in[1];
    const int*   maskp    = (const int*)  d_in[2];
    const float* embed    = (const float*)d_in[3];
    const float* Wt       = (const float*)d_in[4];
    const float* bt       = (const float*)d_in[5];
    const float* Wtc      = (const float*)d_in[6];
    const float* Wq       = (const float*)d_in[7];
    const float* Wd       = (const float*)d_in[8];
    const float* Wo       = (const float*)d_in[9];
    const float* Wu       = (const float*)d_in[10];
    const float* Wem      = (const float*)d_in[11];
    const float* Wkc      = (const float*)d_in[12];
    const float* bkc      = (const float*)d_in[13];
    float* out = (float*)d_out;

    float *xsa,*xsad,*t1p,*pm,*ps,*lse,*tval;
    bf *xsab,*xsat,*acat,*q2b,*yb,*midb;
    bf *wq,*wd,*wot,*wc1,*wc2;
    bf *ehi,*elo,*xhlo,*xtlo,*wkhi,*wklo,*wmhi,*wmlo;
    bf *lphi,*lplo,*x1hi,*x1lo,*shi,*slo,*xxhi,*xxlo,*vhi,*vlo;
    GSYM(xsa,g_xsa); GSYM(xsad,g_xsad); GSYM(t1p,g_t1p);
    GSYM(pm,g_pm); GSYM(ps,g_ps); GSYM(lse,g_lse); GSYM(tval,g_tval);
    GSYM(xsab,g_xsab); GSYM(xsat,g_xsat); GSYM(acat,g_acat);
    GSYM(q2b,g_q2b); GSYM(yb,g_yb); GSYM(midb,g_midb);
    GSYM(wq,g_wq); GSYM(wd,g_wd); GSYM(wot,g_wot); GSYM(wc1,g_wc1); GSYM(wc2,g_wc2);
    GSYM(ehi,g_ehi); GSYM(elo,g_elo); GSYM(xhlo,g_xhlo); GSYM(xtlo,g_xtlo);
    GSYM(wkhi,g_wkhi); GSYM(wklo,g_wklo); GSYM(wmhi,g_wmhi); GSYM(wmlo,g_wmlo);
    GSYM(lphi,g_lphi); GSYM(lplo,g_lplo);
    GSYM(x1hi,g_x1hi); GSYM(x1lo,g_x1lo); GSYM(shi,g_shi); GSYM(slo,g_slo);
    GSYM(xxhi,g_xxhi); GSYM(xxlo,g_xxlo); GSYM(vhi,g_vhi); GSYM(vlo,g_vlo);

    // kernel instantiations
    auto kS1 = bgemm_k<64,64,32,16,128,true ,false,4,2,false,1>;   // K=256 -> 2 iters
    auto kS2 = bgemm_k<64,64,32,16,128,false,true ,0,0,false,0>;   // K=768 -> 6 iters
    auto kWq = bgemm_k<128,128,64,32,64,false,false,1,0,false,1>;
    auto kWd = bgemm_k<128,128,64,32,64,true ,false,0,0,false,1>;
    auto kWo = bgemm_k<64,64,32,16,128,false,false,0,0,false,0>;   // K=512 -> 4 iters
    auto kG1 = bgemm_k<64,64,32,16,64,false,true ,3,0,true ,2>;
    auto kG2 = bgemm_k<64,64,32,16,64,false,false,0,0,true ,2>;
    auto kG3 = bgemm_k<64,64,32,16,64,false,false,0,0,true ,2>;
    auto kG4 = bgemm_k<64,64,32,16,64,false,false,0,0,true ,2>;

    constexpr int SM_BIG64  = 2*(128+128)*36*4;   // 73728 B
    constexpr int SM_SML128 = 2*(64+64)*68*4;     // 69632 B
    constexpr int SM_CMP64  = 2*2*(64+64)*36*4;   // 73728 B
    constexpr int SM_FA     = 2*(64+512)*36*4;    // 165888 B
    constexpr int SM_GLSE   = 2*2*(128+128)*36*4; // 147456 B

    cudaFuncSetAttribute(kS1, cudaFuncAttributeMaxDynamicSharedMemorySize, SM_SML128);
    cudaFuncSetAttribute(kS2, cudaFuncAttributeMaxDynamicSharedMemorySize, SM_SML128);
    cudaFuncSetAttribute(kWo, cudaFuncAttributeMaxDynamicSharedMemorySize, SM_SML128);
    cudaFuncSetAttribute(kWq, cudaFuncAttributeMaxDynamicSharedMemorySize, SM_BIG64);
    cudaFuncSetAttribute(kWd, cudaFuncAttributeMaxDynamicSharedMemorySize, SM_BIG64);
    cudaFuncSetAttribute(kG1, cudaFuncAttributeMaxDynamicSharedMemorySize, SM_CMP64);
    cudaFuncSetAttribute(kG2, cudaFuncAttributeMaxDynamicSharedMemorySize, SM_CMP64);
    cudaFuncSetAttribute(kG3, cudaFuncAttributeMaxDynamicSharedMemorySize, SM_CMP64);
    cudaFuncSetAttribute(kG4, cudaFuncAttributeMaxDynamicSharedMemorySize, SM_CMP64);
    cudaFuncSetAttribute(fa_k, cudaFuncAttributeMaxDynamicSharedMemorySize, SM_FA);
    cudaFuncSetAttribute(glse_k, cudaFuncAttributeMaxDynamicSharedMemorySize, SM_GLSE);

    // ---- prep: bf16 weights (per launch; graph-captured) ----
    prep_w_k<<<(Dd*5*65536+1023)/1024,1024>>>(Wt, Wtc, Wu, wc1, wc2);
    conv_b4<<<((long)Dd*KE*Ee/4+255)/256,256>>>((const float4*)Wq, (uint2*)wq, (long)Dd*KE*Ee/4);
    conv_b4<<<((long)Dd*KE*KE/4+255)/256,256>>>((const float4*)Wd, (uint2*)wd, (long)Dd*KE*KE/4);
    t32_f2b<<<dim3(KE/32,Ee/32,Dd),256>>>(Wo, wot, KE, Ee);
    split_b4<<<((long)Gg*Ee/4+255)/256,256>>>((const float4*)embed, (uint2*)ehi, (uint2*)elo, (long)Gg*Ee/4);
    split_b4<<<(KN*Ee*Ee/4+255)/256,256>>>((const float4*)Wkc, (uint2*)wkhi, (uint2*)wklo, KN*Ee*Ee/4);
    t32_f2b2<<<dim3(Ee/32,Ee/32,1),256>>>(Wem, wmhi, wmlo, Ee, Ee);

    embed_norm_k<<<TOK,256>>>(masked, embed, xsa, xsab, xsat, acat);

    for (int d=0; d<Dd; d++){
        // transitions
        kS1<<<dim3(4,32,2),256,SM_SML128>>>(xsab,0, wc1+(long)d*131072,0, 0, 0,acat,0,
                                            TOK,Ee,Ee, Ee,Ee, 0, 65536, 0, 1);
        kS2<<<dim3(4,32,1),256,SM_SML128>>>(acat,0, wc2+(long)d*196608,0, bt+(long)d*Ee, xsad,0,0,
                                            TOK,Ee,768, 768,768, 0,0,0, 0);

        // attention (fully fused: QK -> softmax -> P@V)
        kWq<<<dim3(16,16,1),256,SM_BIG64>>>(xsab,0, wq+(long)d*KE*Ee,0, 0, 0,q2b,0,
                                            TOK,KE,Ee, Ee,Ee, 0,0,0, 0);
        fa_k<<<dim3(1,64,Bb),512,SM_FA>>>(q2b, xsab, xsat, yb,
                                          (long)Ll*Kk*Ee, (long)Ll*Ee);

        // dense -> relu -> dense (Wo via split-K=4)
        kWd<<<dim3(16,16,1),256,SM_BIG64>>>(yb,0, wd+(long)d*KE*KE,0, 0, 0,midb,0,
                                            TOK,KE,KE, KE,KE, 0,0,0, 0);
        kWo<<<dim3(4,32,4),256,SM_SML128>>>(midb,0, wot+(long)d*Ee*KE,0, 0, t1p,0,0,
                                            TOK,Ee,512, KE,KE, 512, 512, (long)TOK*Ee, 0);

        update_norm_k<<<TOK,256>>>(xsad, t1p, xsa, xsab, xsat);
    }

    // ---- head (split-bf16 3-mma; hi of xsa == xsab/xsat) ----
    split_lo4<<<(TOK*Ee/4+255)/256,256>>>((const float4*)xsa, (uint2*)xhlo, TOK*Ee/4);
    transpose_b<<<dim3(TOK/32,Ee/32),256>>>(xhlo, xtlo, TOK, Ee);
    gather_split_k<<<Bb*LM,256>>>(maskp, xsa, lphi, lplo);

    kG1<<<dim3(16,4,1),256,SM_CMP64>>>(lphi,lplo, wkhi,wklo, bkc, 0,x1hi,x1lo,
                                       Bb*LM, KN*Ee, Ee, Ee,Ee, 0,0,0, 0);
    kG2<<<dim3(8,4,Bb),256,SM_CMP64>>>(x1hi,x1lo, xsab,xhlo, 0, 0,shi,slo,
                                       LM*KN, Ll, Ee, Ee,Ee,
                                       (long)LM*KN*Ee, (long)Ll*Ee, (long)LM*KN*Ll, 0);
    kG3<<<dim3(4,4,Bb),256,SM_CMP64>>>(shi,slo, xsat,xtlo, 0, 0,xxhi,xxlo,
                                       LM*KN, Ee, Ll, Ll,TOK,
                                       (long)LM*KN*Ll, (long)Ll, (long)LM*KN*Ee, 0);
    kG4<<<dim3(4,16,1),256,SM_CMP64>>>(xxhi,xxlo, wmhi,wmlo, 0, 0,vhi,vlo,
                                       Bb*LM*KN, Ee, Ee, Ee,Ee, 0,0,0, 0);

    // fused logits + LSE (no logits buffer), 128x128 tiles, KCH=64
    glse_k<<<dim3(250,8,1),256,SM_GLSE>>>(vhi, vlo, ehi, elo, pm, ps);
    lse_red_k<<<(Bb*LM*KN)/8,256>>>(pm, ps, lse);
    tval_k<<<Bb*LM*KN,256>>>(vhi, vlo, ehi, elo, unmasked, maskp, tval);
    final_k<<<Bb,64>>>(tval, lse, out);
}

// round 16
// speedup vs baseline: 1.0169x; 1.0169x over previous
#include <cuda_runtime.h>
#include <cuda_bf16.h>
#include <math.h>
#include <stdint.h>

// ---------------- problem constants ----------------
#define Bb 4
#define Ll 512
#define Ee 256
#define Kk 8
#define Dd 6
#define LM 64
#define KN 4
#define Gg 32000
#define KE (Kk*Ee)          // 2048
#define TOK (Bb*Ll)         // 2048

typedef __nv_bfloat16 bf;

// ---------------- scratch (static device memory; no allocations) ----------------
__device__ float g_xsa [TOK*Ee];
__device__ float g_xsad[TOK*Ee];
__device__ float g_t1p [4L*TOK*Ee];
__device__ bf    g_xsab[TOK*Ee];
__device__ bf    g_xsat[Ee*TOK];
__device__ bf    g_acat[TOK*768];
__device__ bf    g_q2b [TOK*KE];
__device__ bf    g_yb  [TOK*KE];
__device__ bf    g_midb[TOK*KE];
__device__ bf    g_wq [(long)Dd*KE*Ee];
__device__ bf    g_wd [(long)Dd*KE*KE];
__device__ bf    g_wot[(long)Dd*Ee*KE];
__device__ bf    g_wc1[Dd*2*Ee*Ee];
__device__ bf    g_wc2[Dd*Ee*768];
__device__ bf    g_ehi[(long)Gg*Ee], g_elo[(long)Gg*Ee];
__device__ bf    g_xhlo[TOK*Ee];
__device__ bf    g_xtlo[Ee*TOK];
__device__ bf    g_wkhi[KN*Ee*Ee],g_wklo[KN*Ee*Ee];
__device__ bf    g_wmhi[Ee*Ee],   g_wmlo[Ee*Ee];
__device__ bf    g_lphi[Bb*LM*Ee],g_lplo[Bb*LM*Ee];
__device__ bf    g_x1hi[Bb*LM*KN*Ee], g_x1lo[Bb*LM*KN*Ee];
__device__ bf    g_shi[(long)Bb*LM*KN*Ll], g_slo[(long)Bb*LM*KN*Ll];
__device__ bf    g_xxhi[Bb*LM*KN*Ee], g_xxlo[Bb*LM*KN*Ee];
__device__ bf    g_vhi[Bb*LM*KN*Ee],  g_vlo[Bb*LM*KN*Ee];
__device__ float g_pm[(long)Bb*LM*KN*250];
__device__ float g_ps[(long)Bb*LM*KN*250];
__device__ float g_lse [Bb*LM*KN];
__device__ float g_tval[Bb*LM*KN];

// ---------------- reductions ----------------
__device__ __forceinline__ float warp_sum(float v){
    #pragma unroll
    for (int o=16;o;o>>=1) v += __shfl_xor_sync(0xffffffffu, v, o);
    return v;
}
__device__ float block_sum256(float v){
    __shared__ float sh[8];
    int lane = threadIdx.x & 31, w = threadIdx.x >> 5;
    v = warp_sum(v);
    if (lane==0) sh[w] = v;
    __syncthreads();
    float r = (threadIdx.x < 8) ? sh[threadIdx.x] : 0.f;
    if (w==0){ r = warp_sum(r); if (lane==0) sh[0]=r; }
    __syncthreads();
    float out = sh[0];
    __syncthreads();
    return out;
}

// ---------------- bf16 / mma / cp.async / ldmatrix helpers ----------------
__device__ __forceinline__ uint32_t pk2(float lo, float hi){
    uint32_t r;
    asm("cvt.rn.bf16x2.f32 %0, %1, %2;" : "=r"(r) : "f"(hi), "f"(lo));
    return r;
}
__device__ __forceinline__ void mma_bf16(float* d, const uint32_t* a, const uint32_t* b){
    asm volatile(
      "mma.sync.aligned.m16n8k16.row.col.f32.bf16.bf16.f32 "
      "{%0,%1,%2,%3}, {%4,%5,%6,%7}, {%8,%9}, {%0,%1,%2,%3};\n"
      : "+f"(d[0]),"+f"(d[1]),"+f"(d[2]),"+f"(d[3])
      : "r"(a[0]),"r"(a[1]),"r"(a[2]),"r"(a[3]), "r"(b[0]),"r"(b[1]));
}
__device__ __forceinline__ void cp16b(void* s, const bf* g){
    uint32_t sa = (uint32_t)__cvta_generic_to_shared(s);
    asm volatile("cp.async.ca.shared.global [%0], [%1], 16;\n" :: "r"(sa), "l"(g));
}
__device__ __forceinline__ void cp_commit(){ asm volatile("cp.async.commit_group;\n" ::); }
template<int W> __device__ __forceinline__ void cp_wait(){ asm volatile("cp.async.wait_group %0;\n" :: "n"(W)); }
__device__ __forceinline__ uint32_t s2u(const void* p){
    uint32_t a;
    asm("{ .reg .u64 t; cvta.to.shared.u64 t, %1; cvt.u32.u64 %0, t; }" : "=r"(a) : "l"(p));
    return a;
}
__device__ __forceinline__ void ldsm4(uint32_t& r0, uint32_t& r1, uint32_t& r2, uint32_t& r3,
                                      uint32_t addr){
    asm volatile("ldmatrix.sync.aligned.m8n8.x4.shared.b16 {%0,%1,%2,%3}, [%4];"
        : "=r"(r0),"=r"(r1),"=r"(r2),"=r"(r3) : "r"(addr));
}
__device__ __forceinline__ void ols_merge(float& m, float& s, float mo, float so){
    float mn = fmaxf(m, mo);
    s = s*expf(m - mn) + so*expf(mo - mn);
    m = mn;
}

// PMODE output index mapping (element index):
template<int PMODE>
__device__ __forceinline__ long out_index(int r, int c, int bz, int N, long sC){
    if (PMODE==0) return (long)bz*sC + (long)r*N + c;
    if (PMODE==1) return (((long)(r>>9))<<20) + ((long)(r&511)<<11) + c;
    if (PMODE==2) return (((long)(bz*512 + (r>>3)))<<11) + ((long)(r&7)<<8) + c;
    if (PMODE==3) return (((long)(r>>6))<<16) + ((long)(r&63)<<10) + c;
    return (long)r*768 + ((long)bz<<8) + c;
}

// ---------------- unified bf16 tensor-core GEMM core (device function) ----------------
// KCH: 32 -> pitch 20 / 3-stage; 64 -> pitch 36 / 2-stage.
template<int BM,int BN,int WM,int WN,int KCH,bool RELU,bool BIAS,int PMODE,int ROLLMODE,bool COMP,int OUTMODE>
__device__ __forceinline__
void bgemm_core(const bf* __restrict__ A, const bf* __restrict__ Alo,
                const bf* __restrict__ B, const bf* __restrict__ Blo,
                const float* __restrict__ bias,
                float* __restrict__ C, bf* __restrict__ Cb, bf* __restrict__ Clo,
                int M, int N, int Kd, int lda, int ldb,
                long sA, long sB, long sC, int rollShift,
                int bix, int biy, int biz)
{
    constexpr int P    = KCH/2 + 4;
    constexpr int CH   = KCH/8;
    constexpr int NSTG = (KCH>=64) ? 2 : 3;
    constexpr int NST  = COMP ? 2 : 1;
    constexpr int TA   = BM*P, TB = BN*P;
    constexpr int STG  = NST*(TA+TB);
    constexpr int MI   = WM/16, NI = WN/8;
    constexpr int NJ   = NI/2;
    constexpr int WCOLS = BN/WN;
    constexpr int KS   = KCH/16;

    extern __shared__ uint32_t smw[];
    const uint32_t smem_u = s2u(smw);

    const int bz = biz;
    const bf* Ap  = A + (long)bz*sA;
    const bf* Alp = COMP ? Alo + (long)bz*sA : nullptr;
    const bf* Bp  = B + (long)bz*sB;
    const bf* Blp = COMP ? Blo + (long)bz*sB : nullptr;

    int rs = 0;
    if (ROLLMODE==2) rs = (bz==0) ? rollShift : -rollShift;

    const int row0 = biy*BM, col0 = bix*BN;
    const int tid  = threadIdx.x;
    const int warp = tid >> 5, lane = tid & 31;
    const int wy = warp / WCOLS, wx = warp % WCOLS;
    const int g = lane >> 2, c4 = lane & 3;

    uint32_t aoff[MI];
    #pragma unroll
    for (int mi=0; mi<MI; mi++)
        aoff[mi] = (uint32_t)(((wy*WM + mi*16 + (lane & 15))*P + (lane>>4)*4) * 4);
    uint32_t boff[NJ];
    #pragma unroll
    for (int j=0; j<NJ; j++)
        boff[j] = (uint32_t)(((wx*WN + j*16 + ((lane>>4)<<3) + (lane & 7))*P + ((lane>>3)&1)*4) * 4);

    auto load_tile = [&](int kt, int st){
        uint32_t* base = smw + st*STG;
        uint32_t* Ah = base;
        uint32_t* Al = base + TA;
        uint32_t* Bh = base + NST*TA;
        uint32_t* Bl = Bh + TB;
        const int k0 = kt*KCH;
        #pragma unroll
        for (int i=0;i<BM*CH/256;i++){
            int id = tid + i*256; int r = id/CH, q = id%CH;
            int gr = row0 + r;
            if (ROLLMODE) gr = (gr & ~511) | ((gr - rs) & 511);
            long go = (long)gr*lda + k0 + 8*q;
            cp16b(Ah + r*P + 4*q, Ap + go);
            if (COMP) cp16b(Al + r*P + 4*q, Alp + go);
        }
        #pragma unroll
        for (int i=0;i<BN*CH/256;i++){
            int id = tid + i*256; int n = id/CH, q = id%CH;
            long go = (long)(col0+n)*ldb + k0 + 8*q;
            cp16b(Bh + n*P + 4*q, Bp + go);
            if (COMP) cp16b(Bl + n*P + 4*q, Blp + go);
        }
        cp_commit();
    };

    float acc[MI][NI][4];
    #pragma unroll
    for (int i=0;i<MI;i++)
        #pragma unroll
        for (int j=0;j<NI;j++)
            #pragma unroll
            for (int t=0;t<4;t++) acc[i][j][t]=0.f;

    const int nit = Kd/KCH;
    load_tile(0, 0);
    if (NSTG==3 && nit>1) load_tile(1, 1);

    int st = 0;
    for (int it=0; it<nit; it++){
        if (NSTG==3){
            if (it+2 < nit){ load_tile(it+2, (it+2)%3); cp_wait<2>(); }
            else if (it+1 < nit){ cp_wait<1>(); }
            else { cp_wait<0>(); }
        } else {
            if (it+1 < nit){ load_tile(it+1, (it+1)&1); cp_wait<1>(); }
            else { cp_wait<0>(); }
        }
        __syncthreads();

        const uint32_t AhB = smem_u + (uint32_t)(st*STG*4);
        const uint32_t AlB = AhB + TA*4;
        const uint32_t BhB = AhB + NST*TA*4;
        const uint32_t BlB = BhB + TB*4;

        #pragma unroll
        for (int ks=0; ks<KS; ks++){
            const uint32_t ko = ks*32;
            uint32_t af[MI][4], bfr[NI][2];
            uint32_t afl[COMP?MI:1][4], bfl[COMP?NI:1][2];
            #pragma unroll
            for (int mi=0; mi<MI; mi++){
                ldsm4(af[mi][0], af[mi][1], af[mi][2], af[mi][3], AhB + aoff[mi] + ko);
                if (COMP)
                    ldsm4(afl[mi][0], afl[mi][1], afl[mi][2], afl[mi][3], AlB + aoff[mi] + ko);
            }
            #pragma unroll
            for (int j=0; j<NJ; j++){
                ldsm4(bfr[2*j][0], bfr[2*j][1], bfr[2*j+1][0], bfr[2*j+1][1], BhB + boff[j] + ko);
                if (COMP)
                    ldsm4(bfl[2*j][0], bfl[2*j][1], bfl[2*j+1][0], bfl[2*j+1][1], BlB + boff[j] + ko);
            }
            #pragma unroll
            for (int mi=0; mi<MI; mi++)
                #pragma unroll
                for (int ni=0; ni<NI; ni++){
                    if (COMP){
                        mma_bf16(acc[mi][ni], afl[mi], bfr[ni]);
                        mma_bf16(acc[mi][ni], af[mi], bfl[ni]);
                    }
                    mma_bf16(acc[mi][ni], af[mi], bfr[ni]);
                }
        }
        __syncthreads();
        st = (NSTG==3) ? ((st==2)?0:st+1) : (st^1);
    }

    // ---- epilogue ----
    #pragma unroll
    for (int mi=0; mi<MI; mi++){
        #pragma unroll
        for (int half=0; half<2; half++){
            int r = row0 + wy*WM + mi*16 + g + half*8;
            #pragma unroll
            for (int ni=0; ni<NI; ni++){
                int cc = col0 + wx*WN + ni*8 + 2*c4;
                float v0 = acc[mi][ni][half*2+0];
                float v1 = acc[mi][ni][half*2+1];
                if (BIAS){ v0 += bias[cc]; v1 += bias[cc+1]; }
                if (RELU){ v0 = fmaxf(v0,0.f); v1 = fmaxf(v1,0.f); }
                long idx = out_index<PMODE>(r, cc, bz, N, sC);
                if (OUTMODE==0){
                    *(float2*)(C + idx) = make_float2(v0, v1);
                } else if (OUTMODE==1){
                    *(uint32_t*)(Cb + idx) = pk2(v0, v1);
                } else {
                    bf h0 = __float2bfloat16(v0);
                    bf h1 = __float2bfloat16(v1);
                    union { __nv_bfloat162 b; uint32_t u; } cu;
                    cu.b = __halves2bfloat162(h0, h1);
                    *(uint32_t*)(Cb + idx)  = cu.u;
                    *(uint32_t*)(Clo + idx) = pk2(v0 - __bfloat162float(h0),
                                                  v1 - __bfloat162float(h1));
                }
            }
        }
    }
}

// __global__ wrapper (standalone launches)
template<int BM,int BN,int WM,int WN,int KCH,bool RELU,bool BIAS,int PMODE,int ROLLMODE,bool COMP,int OUTMODE>
__global__ __launch_bounds__(256, 2)
void bgemm_k(const bf* __restrict__ A, const bf* __restrict__ Alo,
             const bf* __restrict__ B, const bf* __restrict__ Blo,
             const float* __restrict__ bias,
             float* __restrict__ C, bf* __restrict__ Cb, bf* __restrict__ Clo,
             int M, int N, int Kd, int lda, int ldb,
             long sA, long sB, long sC, int rollShift)
{
    bgemm_core<BM,BN,WM,WN,KCH,RELU,BIAS,PMODE,ROLLMODE,COMP,OUTMODE>(
        A,Alo,B,Blo,bias,C,Cb,Clo,M,N,Kd,lda,ldb,sA,sB,sC,rollShift,
        blockIdx.x, blockIdx.y, blockIdx.z);
}

// ---------------- combined layer kernels (block-role fusion) ----------------
// layer1: blocks [0,256) run kWq; blocks [256,512) run kS1 (transitions stage1).
__global__ __launch_bounds__(256, 2)
void layer1_k(const bf* __restrict__ xsab, const bf* __restrict__ wqd,
              bf* __restrict__ q2b, const bf* __restrict__ wc1d, bf* __restrict__ acat)
{
    int b = blockIdx.x;
    if (b < 256){
        bgemm_core<128,128,64,32,64,false,false,1,0,false,1>(
            xsab,nullptr, wqd,nullptr, nullptr, nullptr,q2b,nullptr,
            TOK,KE,Ee, Ee,Ee, 0,0,0, 0, b&15, b>>4, 0);
    } else {
        int t = b - 256;
        bgemm_core<64,64,32,16,64,true,false,4,2,false,1>(
            xsab,nullptr, wc1d,nullptr, nullptr, nullptr,acat,nullptr,
            TOK,Ee,Ee, Ee,Ee, 0,65536,0, 1, t&3, (t>>2)&31, t>>7);
    }
}

// layer2: blocks [0,256) run kWd; blocks [256,384) run kS2 (transitions stage2).
__global__ __launch_bounds__(256, 2)
void layer2_k(const bf* __restrict__ yb, const bf* __restrict__ wdd,
              bf* __restrict__ midb, const bf* __restrict__ acat,
              const bf* __restrict__ wc2d, const float* __restrict__ btd,
              float* __restrict__ xsad)
{
    int b = blockIdx.x;
    if (b < 256){
        bgemm_core<128,128,64,32,64,true,false,0,0,false,1>(
            yb,nullptr, wdd,nullptr, nullptr, nullptr,midb,nullptr,
            TOK,KE,KE, KE,KE, 0,0,0, 0, b&15, b>>4, 0);
    } else {
        int t = b - 256;
        bgemm_core<64,64,32,16,64,false,true,0,0,false,0>(
            acat,nullptr, wc2d,nullptr, btd, xsad,nullptr,nullptr,
            TOK,Ee,768, 768,768, 0,0,0, 0, t&3, t>>2, 0);
    }
}

// ---------------- fully fused attention: QK -> softmax -> P@V (R14 version) ----------------
__global__ __launch_bounds__(512, 1)
void fa_k(const bf* __restrict__ A, const bf* __restrict__ B,
          const bf* __restrict__ Vt, bf* __restrict__ Y,
          long sA, long sB)
{
    constexpr int Pw  = 20;
    constexpr int TA1 = 64*Pw, TB1 = 512*Pw, STG1 = TA1+TB1;
    constexpr int PWW = 16*64*Pw;
    constexpr int TB2 = 256*Pw;
    extern __shared__ uint32_t smw[];
    const uint32_t smem_u = s2u(smw);

    const int bz = blockIdx.z;
    const bf* Ap = A + (long)bz*sA;
    const bf* Bp = B + (long)bz*sB;
    const int row0 = blockIdx.y*64;
    const int tid = threadIdx.x, warp = tid>>5, lane = tid&31;
    const int g = lane>>2, c4 = lane&3;
    const int wy = warp>>3, wx = warp&7;

    uint32_t aoff1[2];
    #pragma unroll
    for (int mi=0;mi<2;mi++)
        aoff1[mi] = (uint32_t)(((wy*32 + mi*16 + (lane & 15))*Pw + (lane>>4)*4) * 4);
    uint32_t boff1[4];
    #pragma unroll
    for (int j=0;j<4;j++)
        boff1[j] = (uint32_t)(((wx*64 + j*16 + ((lane>>4)<<3) + (lane & 7))*Pw + ((lane>>3)&1)*4) * 4);

    auto load_tile1 = [&](int kt, int st){
        uint32_t* base = smw + st*STG1;
        uint32_t* Ah = base;
        uint32_t* Bh = base + TA1;
        const int k0 = kt*32;
        if (tid < 256){
            int r = tid>>2, q = tid&3;
            cp16b(Ah + r*Pw + 4*q, Ap + (long)(row0+r)*256 + k0 + 8*q);
        }
        #pragma unroll
        for (int i=0;i<4;i++){
            int id = tid + i*512; int n = id>>2, q = id&3;
            cp16b(Bh + n*Pw + 4*q, Bp + (long)n*256 + k0 + 8*q);
        }
        cp_commit();
    };

    float acc[2][8][4];
    #pragma unroll
    for (int i=0;i<2;i++)
        #pragma unroll
        for (int j=0;j<8;j++)
            #pragma unroll
            for (int t=0;t<4;t++) acc[i][j][t]=0.f;

    {
        const int nit = 8;
        load_tile1(0, 0);
        load_tile1(1, 1);
        int st = 0;
        for (int it=0; it<nit; it++){
            if (it+2 < nit){ load_tile1(it+2, (it+2)%3); cp_wait<2>(); }
            else if (it+1 < nit){ cp_wait<1>(); }
            else { cp_wait<0>(); }
            __syncthreads();

            const uint32_t AhB = smem_u + (uint32_t)(st*STG1*4);
            const uint32_t BhB = AhB + TA1*4;
            #pragma unroll
            for (int ks=0; ks<2; ks++){
                const uint32_t ko = ks*32;
                uint32_t af[2][4], bfr[8][2];
                #pragma unroll
                for (int mi=0; mi<2; mi++)
                    ldsm4(af[mi][0], af[mi][1], af[mi][2], af[mi][3], AhB + aoff1[mi] + ko);
                #pragma unroll
                for (int j=0; j<4; j++)
                    ldsm4(bfr[2*j][0], bfr[2*j][1], bfr[2*j+1][0], bfr[2*j+1][1], BhB + boff1[j] + ko);
                #pragma unroll
                for (int mi=0; mi<2; mi++)
                    #pragma unroll
                    for (int ni=0; ni<8; ni++)
                        mma_bf16(acc[mi][ni], af[mi], bfr[ni]);
            }
            __syncthreads();
            st = (st==2) ? 0 : st+1;
        }
    }

    float* red_m = (float*)(smw + PWW + 2*TB2);
    float* red_s = red_m + 64*8;
    #pragma unroll
    for (int mi=0; mi<2; mi++){
        #pragma unroll
        for (int half=0; half<2; half++){
            float mx = -INFINITY;
            #pragma unroll
            for (int ni=0; ni<8; ni++)
                mx = fmaxf(mx, fmaxf(acc[mi][ni][half*2], acc[mi][ni][half*2+1]));
            mx *= 0.0625f;
            float s = 0.f;
            #pragma unroll
            for (int ni=0; ni<8; ni++){
                s += expf(acc[mi][ni][half*2+0]*0.0625f - mx);
                s += expf(acc[mi][ni][half*2+1]*0.0625f - mx);
            }
            float m = mx;
            #pragma unroll
            for (int o=1; o<=2; o<<=1){
                float mo = __shfl_xor_sync(0xffffffffu, m, o);
                float so = __shfl_xor_sync(0xffffffffu, s, o);
                ols_merge(m, s, mo, so);
            }
            int rt = wy*32 + mi*16 + half*8 + g;
            if (c4==0){ red_m[rt*8+wx] = m; red_s[rt*8+wx] = s; }
        }
    }
    __syncthreads();
    if (tid < 64){
        float M = red_m[tid*8], S = red_s[tid*8];
        #pragma unroll
        for (int i=1;i<8;i++) ols_merge(M, S, red_m[tid*8+i], red_s[tid*8+i]);
        red_m[tid*8] = M;
        red_s[tid*8] = 1.f/S;
    }
    __syncthreads();
    #pragma unroll
    for (int mi=0; mi<2; mi++){
        #pragma unroll
        for (int half=0; half<2; half++){
            int rt = wy*32 + mi*16 + half*8 + g;
            float M = red_m[rt*8], inv = red_s[rt*8];
            #pragma unroll
            for (int ni=0; ni<8; ni++){
                int c = wx*64 + ni*8 + 2*c4;
                float p0 = expf(acc[mi][ni][half*2+0]*0.0625f - M)*inv;
                float p1 = expf(acc[mi][ni][half*2+1]*0.0625f - M)*inv;
                smw[(c>>5)*(64*Pw) + rt*Pw + ((c&31)>>1)] = pk2(p0, p1);
            }
        }
    }
    __syncthreads();

    const int wx2 = warp&7, wy2 = warp>>3;
    uint32_t aoff2[2];
    #pragma unroll
    for (int mi=0;mi<2;mi++)
        aoff2[mi] = (uint32_t)(((wy2*32 + mi*16 + (lane & 15))*Pw + (lane>>4)*4) * 4);
    uint32_t boff2a[2];
    #pragma unroll
    for (int j=0;j<2;j++)
        boff2a[j] = (uint32_t)(((wx2*32 + j*16 + ((lane>>4)<<3) + (lane & 7))*Pw + ((lane>>3)&1)*4) * 4);

    auto load_v = [&](int kt, int st){
        uint32_t* Bh = smw + PWW + st*TB2;
        const int k0 = kt*32;
        #pragma unroll
        for (int i=0;i<2;i++){
            int id = tid + i*512; int n = id>>2, q = id&3;
            cp16b(Bh + n*Pw + 4*q, Vt + (long)n*TOK + bz*512 + k0 + 8*q);
        }
        cp_commit();
    };

    float acc2[2][4][4];
    #pragma unroll
    for (int i=0;i<2;i++)
        #pragma unroll
        for (int j=0;j<4;j++)
            #pragma unroll
            for (int t=0;t<4;t++) acc2[i][j][t]=0.f;

    {
        const int nit = 16;
        load_v(0, 0);
        int st = 0;
        for (int it=0; it<nit; it++){
            if (it+1 < nit){ load_v(it+1, st^1); cp_wait<1>(); }
            else { cp_wait<0>(); }
            __syncthreads();

            const uint32_t AB = smem_u + (uint32_t)(it*64*Pw*4);
            const uint32_t BB = smem_u + (uint32_t)((PWW + st*TB2)*4);
            #pragma unroll
            for (int ks=0; ks<2; ks++){
                const uint32_t ko = ks*32;
                uint32_t af[2][4], bfr[4][2];
                #pragma unroll
                for (int mi=0; mi<2; mi++)
                    ldsm4(af[mi][0], af[mi][1], af[mi][2], af[mi][3], AB + aoff2[mi] + ko);
                #pragma unroll
                for (int j=0; j<2; j++)
                    ldsm4(bfr[2*j][0], bfr[2*j][1], bfr[2*j+1][0], bfr[2*j+1][1], BB + boff2a[j] + ko);
                #pragma unroll
                for (int mi=0; mi<2; mi++)
                    #pragma unroll
                    for (int ni=0; ni<4; ni++)
                        mma_bf16(acc2[mi][ni], af[mi], bfr[ni]);
            }
            __syncthreads();
            st ^= 1;
        }
    }

    #pragma unroll
    for (int mi=0; mi<2; mi++){
        #pragma unroll
        for (int half=0; half<2; half++){
            int r = row0 + wy2*32 + mi*16 + g + half*8;
            #pragma unroll
            for (int ni=0; ni<4; ni++){
                int cc = wx2*32 + ni*8 + 2*c4;
                long idx = (((long)(bz*512 + (r>>3)))<<11) + ((long)(r&7)<<8) + cc;
                *(uint32_t*)(Y + idx) = pk2(acc2[mi][ni][half*2+0], acc2[mi][ni][half*2+1]);
            }
        }
    }
}

// ---------------- fused logits GEMM + online-LSE partials (COMP, 128x128, KCH=64) ----------------
__global__ __launch_bounds__(256, 1)
void glse_k(const bf* __restrict__ A, const bf* __restrict__ Alo,
            const bf* __restrict__ B, const bf* __restrict__ Blo,
            float* __restrict__ pm, float* __restrict__ ps)
{
    constexpr int Pw = 36;
    constexpr int TA = 128*Pw, TB = 128*Pw;
    constexpr int STG = 2*(TA+TB);
    extern __shared__ uint32_t smw[];
    const uint32_t smem_u = s2u(smw);

    const int row0 = blockIdx.y*128, col0 = blockIdx.x*128, bx = blockIdx.x;
    const int tid = threadIdx.x, warp = tid>>5, lane = tid&31;
    const int wy = warp>>2, wx = warp&3;
    const int g = lane>>2, c4 = lane&3;

    uint32_t aoff[4];
    #pragma unroll
    for (int mi=0;mi<4;mi++)
        aoff[mi] = (uint32_t)(((wy*64 + mi*16 + (lane & 15))*Pw + (lane>>4)*4) * 4);
    uint32_t boff[2];
    #pragma unroll
    for (int j=0;j<2;j++)
        boff[j] = (uint32_t)(((wx*32 + j*16 + ((lane>>4)<<3) + (lane & 7))*Pw + ((lane>>3)&1)*4) * 4);

    auto load_tile = [&](int kt, int st){
        uint32_t* base = smw + st*STG;
        uint32_t* Ah = base;
        uint32_t* Al = base + TA;
        uint32_t* Bh = base + 2*TA;
        uint32_t* Bl = Bh + TB;
        const int k0 = kt*64;
        #pragma unroll
        for (int i=0;i<4;i++){
            int id = tid + i*256; int r = id>>3, q = id&7;
            long go = (long)(row0+r)*256 + k0 + 8*q;
            cp16b(Ah + r*Pw + 4*q, A + go);
            cp16b(Al + r*Pw + 4*q, Alo + go);
            long gb = (long)(col0+r)*256 + k0 + 8*q;
            cp16b(Bh + r*Pw + 4*q, B + gb);
            cp16b(Bl + r*Pw + 4*q, Blo + gb);
        }
        cp_commit();
    };

    float acc[4][4][4];
    #pragma unroll
    for (int i=0;i<4;i++)
        #pragma unroll
        for (int j=0;j<4;j++)
            #pragma unroll
            for (int t=0;t<4;t++) acc[i][j][t]=0.f;

    const int nit = 4;
    load_tile(0, 0);
    int st = 0;
    for (int it=0; it<nit; it++){
        if (it+1 < nit){ load_tile(it+1, (it+1)&1); cp_wait<1>(); }
        else { cp_wait<0>(); }
        __syncthreads();

        const uint32_t AhB = smem_u + (uint32_t)(st*STG*4);
        const uint32_t AlB = AhB + TA*4;
        const uint32_t BhB = AhB + 2*TA*4;
        const uint32_t BlB = BhB + TB*4;
        #pragma unroll
        for (int ks=0; ks<4; ks++){
            const uint32_t ko = ks*32;
            uint32_t af[4][4], afl[4][4], bfr[4][2], bfl[4][2];
            #pragma unroll
            for (int mi=0; mi<4; mi++){
                ldsm4(af[mi][0], af[mi][1], af[mi][2], af[mi][3], AhB + aoff[mi] + ko);
                ldsm4(afl[mi][0], afl[mi][1], afl[mi][2], afl[mi][3], AlB + aoff[mi] + ko);
            }
            #pragma unroll
            for (int j=0; j<2; j++){
                ldsm4(bfr[2*j][0], bfr[2*j][1], bfr[2*j+1][0], bfr[2*j+1][1], BhB + boff[j] + ko);
                ldsm4(bfl[2*j][0], bfl[2*j][1], bfl[2*j+1][0], bfl[2*j+1][1], BlB + boff[j] + ko);
            }
            #pragma unroll
            for (int mi=0; mi<4; mi++)
                #pragma unroll
                for (int ni=0; ni<4; ni++){
                    mma_bf16(acc[mi][ni], afl[mi], bfr[ni]);
                    mma_bf16(acc[mi][ni], af[mi], bfl[ni]);
                    mma_bf16(acc[mi][ni], af[mi], bfr[ni]);
                }
        }
        __syncthreads();
        st ^= 1;
    }

    float* red_m = (float*)smw;
    float* red_s = red_m + 128*4;
    #pragma unroll
    for (int mi=0; mi<4; mi++){
        #pragma unroll
        for (int half=0; half<2; half++){
            float mx = -INFINITY;
            #pragma unroll
            for (int ni=0; ni<4; ni++)
                mx = fmaxf(mx, fmaxf(acc[mi][ni][half*2], acc[mi][ni][half*2+1]));
            float s = 0.f;
            #pragma unroll
            for (int ni=0; ni<4; ni++){
                s += expf(acc[mi][ni][half*2+0]-mx);
                s += expf(acc[mi][ni][half*2+1]-mx);
            }
            float m = mx;
            #pragma unroll
            for (int o=1; o<=2; o<<=1){
                float mo = __shfl_xor_sync(0xffffffffu, m, o);
                float so = __shfl_xor_sync(0xffffffffu, s, o);
                ols_merge(m, s, mo, so);
            }
            int rt = wy*64 + mi*16 + half*8 + g;
            if (c4==0){ red_m[rt*4+wx] = m; red_s[rt*4+wx] = s; }
        }
    }
    __syncthreads();
    if (tid < 128){
        float M = red_m[tid*4], S = red_s[tid*4];
        #pragma unroll
        for (int i=1;i<4;i++) ols_merge(M, S, red_m[tid*4+i], red_s[tid*4+i]);
        long idx = (long)(row0+tid)*250 + bx;
        pm[idx] = M;
        ps[idx] = S;
    }
}

// merge 250 partials per row -> lse
__global__ void lse_red_k(const float* __restrict__ pm, const float* __restrict__ ps,
                          float* __restrict__ lse){
    int row = blockIdx.x*8 + (threadIdx.x>>5);
    int lane = threadIdx.x & 31;
    float m = -INFINITY, s = 0.f;
    for (int i=lane; i<250; i+=32)
        ols_merge(m, s, pm[(long)row*250+i], ps[(long)row*250+i]);
    #pragma unroll
    for (int o=16;o;o>>=1){
        float mo = __shfl_xor_sync(0xffffffffu, m, o);
        float so = __shfl_xor_sync(0xffffffffu, s, o);
        ols_merge(m, s, mo, so);
    }
    if (lane==0) lse[row] = m + logf(s);
}

// exact fp32 target logit
__global__ void tval_k(const bf* __restrict__ vhi, const bf* __restrict__ vlo,
                       const bf* __restrict__ ehi, const bf* __restrict__ elo,
                       const int* __restrict__ unmasked, const int* __restrict__ mask,
                       float* __restrict__ tval){
    int row = blockIdx.x;
    int b = row >> 8, n = row & 255, j = n >> 2;
    int tg = unmasked[b*Ll + mask[b*LM + j]];
    long vi = (long)row*Ee + threadIdx.x;
    long ei = (long)tg*Ee + threadIdx.x;
    float v = (__bfloat162float(vhi[vi]) + __bfloat162float(vlo[vi]))
            * (__bfloat162float(ehi[ei]) + __bfloat162float(elo[ei]));
    float s = block_sum256(v);
    if (threadIdx.x==0) tval[row] = s;
}

// ---------------- prep kernels ----------------
__global__ void prep_w_k(const float* __restrict__ Wt, const float* __restrict__ Wtc,
                         const float* __restrict__ Wu,
                         bf* __restrict__ wc1, bf* __restrict__ wc2)
{
    long idx = (long)blockIdx.x*1024 + threadIdx.x;
    if (idx >= (long)Dd*5*65536) return;
    int d = idx / (5*65536);
    int r = idx % (5*65536);
    int which = r / 65536;
    int e = r % 65536;
    int n = e >> 8, k = e & 255;
    long wb = (long)d*65536;
    if      (which==0) wc1[(long)d*131072 +         n*256+k] = __float2bfloat16(Wt [wb + (long)k*256 + n]);
    else if (which==1) wc1[(long)d*131072 + 65536 + n*256+k] = __float2bfloat16(Wtc[wb + (long)n*256 + k]);
    else if (which==2) wc2[(long)d*196608 + (long)n*768 +       k] = __float2bfloat16(Wtc[wb + (long)k*256 + n]);
    else if (which==3) wc2[(long)d*196608 + (long)n*768 + 256 + k] = __float2bfloat16(Wt [wb + (long)n*256 + k]);
    else               wc2[(long)d*196608 + (long)n*768 + 512 + k] = __float2bfloat16(Wu [wb + (long)n*256 + k]);
}

__global__ void conv_b4(const float4* __restrict__ in, uint2* __restrict__ outp, long n4){
    long i = (long)blockIdx.x*256 + threadIdx.x;
    if (i >= n4) return;
    float4 v = in[i];
    uint2 o; o.x = pk2(v.x, v.y); o.y = pk2(v.z, v.w);
    outp[i] = o;
}

__global__ void split_b4(const float4* __restrict__ in, uint2* __restrict__ hi,
                         uint2* __restrict__ lo, long n4){
    long i = (long)blockIdx.x*256 + threadIdx.x;
    if (i >= n4) return;
    float4 v = in[i];
    bf hx=__float2bfloat16(v.x), hy=__float2bfloat16(v.y);
    bf hz=__float2bfloat16(v.z), hw=__float2bfloat16(v.w);
    union { __nv_bfloat162 b; uint32_t u; } c0, c1;
    c0.b = __halves2bfloat162(hx, hy);
    c1.b = __halves2bfloat162(hz, hw);
    uint2 h; h.x=c0.u; h.y=c1.u;
    uint2 l;
    l.x = pk2(v.x-__bfloat162float(hx), v.y-__bfloat162float(hy));
    l.y = pk2(v.z-__bfloat162float(hz), v.w-__bfloat162float(hw));
    hi[i]=h; lo[i]=l;
}

__global__ void split_lo4(const float4* __restrict__ in, uint2* __restrict__ lo, long n4){
    long i = (long)blockIdx.x*256 + threadIdx.x;
    if (i >= n4) return;
    float4 v = in[i];
    bf hx=__float2bfloat16(v.x), hy=__float2bfloat16(v.y);
    bf hz=__float2bfloat16(v.z), hw=__float2bfloat16(v.w);
    uint2 l;
    l.x = pk2(v.x-__bfloat162float(hx), v.y-__bfloat162float(hy));
    l.y = pk2(v.z-__bfloat162float(hz), v.w-__bfloat162float(hw));
    lo[i]=l;
}

__global__ void t32_f2b(const float* __restrict__ src, bf* __restrict__ dst, int R, int C){
    __shared__ bf t[32][33];
    const float* s = src + (long)blockIdx.z*R*C;
    bf* d = dst + (long)blockIdx.z*R*C;
    int r0 = blockIdx.x*32, c0 = blockIdx.y*32;
    int tx = threadIdx.x & 31, ty = threadIdx.x >> 5;
    #pragma unroll
    for (int i=0;i<4;i++) t[ty+8*i][tx] = __float2bfloat16(s[(long)(r0+ty+8*i)*C + c0+tx]);
    __syncthreads();
    #pragma unroll
    for (int i=0;i<4;i++) d[(long)(c0+ty+8*i)*R + r0+tx] = t[tx][ty+8*i];
}

__global__ void t32_f2b2(const float* __restrict__ src, bf* __restrict__ dh,
                         bf* __restrict__ dl, int R, int C){
    __shared__ bf th[32][33];
    __shared__ bf tl[32][33];
    int r0 = blockIdx.x*32, c0 = blockIdx.y*32;
    int tx = threadIdx.x & 31, ty = threadIdx.x >> 5;
    #pragma unroll
    for (int i=0;i<4;i++){
        float v = src[(long)(r0+ty+8*i)*C + c0+tx];
        bf h = __float2bfloat16(v);
        th[ty+8*i][tx] = h;
        tl[ty+8*i][tx] = __float2bfloat16(v - __bfloat162float(h));
    }
    __syncthreads();
    #pragma unroll
    for (int i=0;i<4;i++){
        dh[(long)(c0+ty+8*i)*R + r0+tx] = th[tx][ty+8*i];
        dl[(long)(c0+ty+8*i)*R + r0+tx] = tl[tx][ty+8*i];
    }
}

__global__ void transpose_b(const bf* __restrict__ src, bf* __restrict__ dst, int R, int C){
    __shared__ bf t[32][33];
    int r0 = blockIdx.x*32, c0 = blockIdx.y*32;
    int tx = threadIdx.x & 31, ty = threadIdx.x >> 5;
    #pragma unroll
    for (int i=0;i<4;i++) t[ty+8*i][tx] = src[(long)(r0+ty+8*i)*C + c0+tx];
    __syncthreads();
    #pragma unroll
    for (int i=0;i<4;i++) dst[(long)(c0+ty+8*i)*R + r0+tx] = t[tx][ty+8*i];
}

// ---------------- elementwise / reduction kernels ----------------
__global__ void embed_norm_k(const int* __restrict__ masked, const float* __restrict__ embed,
                             float* __restrict__ xsa, bf* __restrict__ xsab,
                             bf* __restrict__ xsat, bf* __restrict__ acat)
{
    int t = blockIdx.x;
    int g = masked[t];
    float v = embed[(long)g*Ee + threadIdx.x];
    float mean = block_sum256(v) * (1.f/Ee);
    float d = v - mean;
    float var = block_sum256(d*d) * (1.f/(Ee-1));
    float o = v / (1.f + sqrtf(var));
    xsa [(long)t*Ee + threadIdx.x] = o;
    bf ob = __float2bfloat16(o);
    xsab[(long)t*Ee + threadIdx.x] = ob;
    xsat[(long)threadIdx.x*TOK + t] = ob;
    acat[(long)t*768 + 512 + threadIdx.x] = ob;
}

__global__ void update_norm_k(const float* __restrict__ xsad, const float* __restrict__ t1p,
                              float* __restrict__ xsa, bf* __restrict__ xsab,
                              bf* __restrict__ xsat)
{
    long idx = (long)blockIdx.x*Ee + threadIdx.x;
    const long S = (long)TOK*Ee;
    float u = xsad[idx] + t1p[idx] + t1p[idx+S] + t1p[idx+2*S] + t1p[idx+3*S];
    float mean = block_sum256(u) * (1.f/Ee);
    float d = u - mean;
    float var = block_sum256(d*d) * (1.f/(Ee-1));
    float un = u / (1.f + sqrtf(var));
    float w = xsa[idx] + 0.05f * un;
    float mean2 = block_sum256(w) * (1.f/Ee);
    float d2 = w - mean2;
    float var2 = block_sum256(d2*d2) * (1.f/(Ee-1));
    float o = w / (1.f + sqrtf(var2));
    xsa[idx]  = o;
    bf ob = __float2bfloat16(o);
    xsab[idx] = ob;
    xsat[(long)threadIdx.x*TOK + blockIdx.x] = ob;
}

__global__ void gather_split_k(const int* __restrict__ mask, const float* __restrict__ xsa,
                               bf* __restrict__ hi, bf* __restrict__ lo){
    int r = blockIdx.x; int b = r >> 6; int p = mask[r];
    float v = xsa[(long)(b*Ll + p)*Ee + threadIdx.x];
    bf h = __float2bfloat16(v);
    hi[(long)r*Ee + threadIdx.x] = h;
    lo[(long)r*Ee + threadIdx.x] = __float2bfloat16(v - __bfloat162float(h));
}

__global__ void final_k(const float* __restrict__ tval, const float* __restrict__ lse,
                        float* __restrict__ out)
{
    int b = blockIdx.x, j = threadIdx.x;
    float a[KN]; float m = -INFINITY;
    #pragma unroll
    for (int kn=0;kn<KN;kn++){
        int r = ((b << 6) + j) * KN + kn;
        a[kn] = tval[r] - lse[r];
        m = fmaxf(m, a[kn]);
    }
    float s = 0.f;
    #pragma unroll
    for (int kn=0;kn<KN;kn++) s += expf(a[kn] - m);
    float cent = m + logf(s) - 1.3862943611198906f;
    __shared__ float sh[64];
    sh[j] = cent; __syncthreads();
    for (int o=32;o;o>>=1){ if (j<o) sh[j] += sh[j+o]; __syncthreads(); }
    if (j==0) out[b] = -sh[0] / (float)LM;
}

// ---------------- host orchestration ----------------
#define GSYM(p, s) cudaGetSymbolAddress((void**)&p, s)

extern "C" void kernel_launch(void* const* d_in, const int* in_sizes, int n_in,
                              void* d_out, int out_size)
{
    (void)in_sizes; (void)n_in; (void)out_size;
    const int*   masked   = (const int*)  d_in[0];
    const int*   unmasked = (const int*)  d_in[1];
    const int*   maskp    = (const int*)  d_in[2];
    const float* embed    = (const float*)d_in[3];
    const float* Wt       = (const float*)d_in[4];
    const float* bt       = (const float*)d_in[5];
    const float* Wtc      = (const float*)d_in[6];
    const float* Wq       = (const float*)d_in[7];
    const float* Wd       = (const float*)d_in[8];
    const float* Wo       = (const float*)d_in[9];
    const float* Wu       = (const float*)d_in[10];
    const float* Wem      = (const float*)d_in[11];
    const float* Wkc      = (const float*)d_in[12];
    const float* bkc      = (const float*)d_in[13];
    float* out = (float*)d_out;

    float *xsa,*xsad,*t1p,*pm,*ps,*lse,*tval;
    bf *xsab,*xsat,*acat,*q2b,*yb,*midb;
    bf *wq,*wd,*wot,*wc1,*wc2;
    bf *ehi,*elo,*xhlo,*xtlo,*wkhi,*wklo,*wmhi,*wmlo;
    bf *lphi,*lplo,*x1hi,*x1lo,*shi,*slo,*xxhi,*xxlo,*vhi,*vlo;
    GSYM(xsa,g_xsa); GSYM(xsad,g_xsad); GSYM(t1p,g_t1p);
    GSYM(pm,g_pm); GSYM(ps,g_ps); GSYM(lse,g_lse); GSYM(tval,g_tval);
    GSYM(xsab,g_xsab); GSYM(xsat,g_xsat); GSYM(acat,g_acat);
    GSYM(q2b,g_q2b); GSYM(yb,g_yb); GSYM(midb,g_midb);
    GSYM(wq,g_wq); GSYM(wd,g_wd); GSYM(wot,g_wot); GSYM(wc1,g_wc1); GSYM(wc2,g_wc2);
    GSYM(ehi,g_ehi); GSYM(elo,g_elo); GSYM(xhlo,g_xhlo); GSYM(xtlo,g_xtlo);
    GSYM(wkhi,g_wkhi); GSYM(wklo,g_wklo); GSYM(wmhi,g_wmhi); GSYM(wmlo,g_wmlo);
    GSYM(lphi,g_lphi); GSYM(lplo,g_lplo);
    GSYM(x1hi,g_x1hi); GSYM(x1lo,g_x1lo); GSYM(shi,g_shi); GSYM(slo,g_slo);
    GSYM(xxhi,g_xxhi); GSYM(xxlo,g_xxlo); GSYM(vhi,g_vhi); GSYM(vlo,g_vlo);

    // standalone kernels (R14 configuration)
    auto kWo = bgemm_k<64,64,32,16,64,false,false,0,0,false,0>;
    auto kG1 = bgemm_k<64,64,32,16,64,false,true ,3,0,true ,2>;
    auto kG2 = bgemm_k<64,64,32,16,64,false,false,0,0,true ,2>;
    auto kG3 = bgemm_k<64,64,32,16,64,false,false,0,0,true ,2>;
    auto kG4 = bgemm_k<64,64,32,16,64,false,false,0,0,true ,2>;

    constexpr int SM_BIG64 = 2*(128+128)*36*4;   // 73728 B (also for combined kernels)
    constexpr int SM_SML64 = 2*(64+64)*36*4;     // 36864 B
    constexpr int SM_CMP64 = 2*2*(64+64)*36*4;   // 73728 B
    constexpr int SM_FA    = 3*(64+512)*20*4;    // 138240 B
    constexpr int SM_GLSE  = 2*2*(128+128)*36*4; // 147456 B

    cudaFuncSetAttribute(layer1_k, cudaFuncAttributeMaxDynamicSharedMemorySize, SM_BIG64);
    cudaFuncSetAttribute(layer2_k, cudaFuncAttributeMaxDynamicSharedMemorySize, SM_BIG64);
    cudaFuncSetAttribute(kWo, cudaFuncAttributeMaxDynamicSharedMemorySize, SM_SML64);
    cudaFuncSetAttribute(kG1, cudaFuncAttributeMaxDynamicSharedMemorySize, SM_CMP64);
    cudaFuncSetAttribute(kG2, cudaFuncAttributeMaxDynamicSharedMemorySize, SM_CMP64);
    cudaFuncSetAttribute(kG3, cudaFuncAttributeMaxDynamicSharedMemorySize, SM_CMP64);
    cudaFuncSetAttribute(kG4, cudaFuncAttributeMaxDynamicSharedMemorySize, SM_CMP64);
    cudaFuncSetAttribute(fa_k, cudaFuncAttributeMaxDynamicSharedMemorySize, SM_FA);
    cudaFuncSetAttribute(glse_k, cudaFuncAttributeMaxDynamicSharedMemorySize, SM_GLSE);

    // ---- prep: bf16 weights (per launch; graph-captured) ----
    prep_w_k<<<(Dd*5*65536+1023)/1024,1024>>>(Wt, Wtc, Wu, wc1, wc2);
    conv_b4<<<((long)Dd*KE*Ee/4+255)/256,256>>>((const float4*)Wq, (uint2*)wq, (long)Dd*KE*Ee/4);
    conv_b4<<<((long)Dd*KE*KE/4+255)/256,256>>>((const float4*)Wd, (uint2*)wd, (long)Dd*KE*KE/4);
    t32_f2b<<<dim3(KE/32,Ee/32,Dd),256>>>(Wo, wot, KE, Ee);
    split_b4<<<((long)Gg*Ee/4+255)/256,256>>>((const float4*)embed, (uint2*)ehi, (uint2*)elo, (long)Gg*Ee/4);
    split_b4<<<(KN*Ee*Ee/4+255)/256,256>>>((const float4*)Wkc, (uint2*)wkhi, (uint2*)wklo, KN*Ee*Ee/4);
    t32_f2b2<<<dim3(Ee/32,Ee/32,1),256>>>(Wem, wmhi, wmlo, Ee, Ee);

    embed_norm_k<<<TOK,256>>>(masked, embed, xsa, xsab, xsat, acat);

    for (int d=0; d<Dd; d++){
        // [kWq | kS1] fused: independent given xsab
        layer1_k<<<512,256,SM_BIG64>>>(xsab, wq+(long)d*KE*Ee, q2b,
                                       wc1+(long)d*131072, acat);
        // attention (fully fused: QK -> softmax -> P@V)
        fa_k<<<dim3(1,64,Bb),512,SM_FA>>>(q2b, xsab, xsat, yb,
                                          (long)Ll*Kk*Ee, (long)Ll*Ee);
        // [kWd | kS2] fused: kWd needs yb (fa), kS2 needs acat (layer1)
        layer2_k<<<384,256,SM_BIG64>>>(yb, wd+(long)d*KE*KE, midb,
                                       acat, wc2+(long)d*196608, bt+(long)d*Ee, xsad);
        // Wo via split-K=4
        kWo<<<dim3(4,32,4),256,SM_SML64>>>(midb,0, wot+(long)d*Ee*KE,0, 0, t1p,0,0,
                                           TOK,Ee,512, KE,KE, 512, 512, (long)TOK*Ee, 0);

        update_norm_k<<<TOK,256>>>(xsad, t1p, xsa, xsab, xsat);
    }

    // ---- head (split-bf16 3-mma; hi of xsa == xsab/xsat) ----
    split_lo4<<<(TOK*Ee/4+255)/256,256>>>((const float4*)xsa, (uint2*)xhlo, TOK*Ee/4);
    transpose_b<<<dim3(TOK/32,Ee/32),256>>>(xhlo, xtlo, TOK, Ee);
    gather_split_k<<<Bb*LM,256>>>(maskp, xsa, lphi, lplo);

    kG1<<<dim3(16,4,1),256,SM_CMP64>>>(lphi,lplo, wkhi,wklo, bkc, 0,x1hi,x1lo,
                                       Bb*LM, KN*Ee, Ee, Ee,Ee, 0,0,0, 0);
    kG2<<<dim3(8,4,Bb),256,SM_CMP64>>>(x1hi,x1lo, xsab,xhlo, 0, 0,shi,slo,
                                       LM*KN, Ll, Ee, Ee,Ee,
                                       (long)LM*KN*Ee, (long)Ll*Ee, (long)LM*KN*Ll, 0);
    kG3<<<dim3(4,4,Bb),256,SM_CMP64>>>(shi,slo, xsat,xtlo, 0, 0,xxhi,xxlo,
                                       LM*KN, Ee, Ll, Ll,TOK,
                                       (long)LM*KN*Ll, (long)Ll, (long)LM*KN*Ee, 0);
    kG4<<<dim3(4,16,1),256,SM_CMP64>>>(xxhi,xxlo, wmhi,wmlo, 0, 0,vhi,vlo,
                                       Bb*LM*KN, Ee, Ee, Ee,Ee, 0,0,0, 0);

    // fused logits + LSE (no logits buffer), 128x128 tiles, KCH=64
    glse_k<<<dim3(250,8,1),256,SM_GLSE>>>(vhi, vlo, ehi, elo, pm, ps);
    lse_red_k<<<(Bb*LM*KN)/8,256>>>(pm, ps, lse);
    tval_k<<<Bb*LM*KN,256>>>(vhi, vlo, ehi, elo, unmasked, maskp, tval);
    final_k<<<Bb,64>>>(tval, lse, out);
}